// round 12
// baseline (speedup 1.0000x reference)
#include <cuda_runtime.h>
#include <cuda_bf16.h>
#include <cuda_fp16.h>
#include <cstdint>
#include <cstddef>

// Problem constants
#define S_TOT  8192
#define HID    1152
#define NH     16
#define HD     72
#define NSEG   8
#define LSEG   1024
#define H3     3456
#define ATT_SCALE 0.11785113019775793f   // 72^-0.5
#define LOG2E     1.4426950408889634f
#define QSCALE    (ATT_SCALE * LOG2E)    // softmax in exp2 domain
#define KP     3456                      // expanded K' = 3*1152 (bf16x3 folded into K)
#define NST    (KP / 32)                 // 108 k-stages of 32
#define QKP    224                       // attention Q'/K' depth: 3*72=216 pad to 224

// Scratch (allocation-free rule: __device__ globals)
__device__ float g_qkv[(size_t)S_TOT * H3];              // 113 MB
__device__ __nv_bfloat16 g_ap[(size_t)S_TOT * KP];       // A' [M][3K]
__device__ __nv_bfloat16 g_wqp[(size_t)H3 * KP];         // Wqkv'T
__device__ __nv_bfloat16 g_wop[(size_t)HID * KP];        // Wout'T
__device__ __nv_bfloat16 g_qp[(size_t)S_TOT * NH * QKP]; // Q' [s][h][224]
__device__ __nv_bfloat16 g_kp2[(size_t)S_TOT * NH * QKP];// K' [s][h][224]
__device__ __half        g_vh[(size_t)S_TOT * NH * 80];  // V fp16 [s][h][80]

// ===========================================================================
// PTX helpers (portable sm_80-class only — no tcgen05 on compute_103)
// ===========================================================================
__device__ __forceinline__ uint32_t smem_u32(const void* p) {
    uint32_t a;
    asm("{ .reg .u64 t; cvta.to.shared.u64 t, %1; cvt.u32.u64 %0, t; }"
        : "=r"(a) : "l"(p));
    return a;
}
__device__ __forceinline__ void cp_async16(uint32_t s, const void* g) {
    asm volatile("cp.async.cg.shared.global [%0], [%1], 16;" :: "r"(s), "l"(g));
}
#define CP_COMMIT() asm volatile("cp.async.commit_group;" ::: "memory")
#define CP_WAIT0()  asm volatile("cp.async.wait_group 0;" ::: "memory")
#define CP_WAIT1()  asm volatile("cp.async.wait_group 1;" ::: "memory")

__device__ __forceinline__ void ldm_x4(uint32_t addr, uint32_t& r0, uint32_t& r1,
                                       uint32_t& r2, uint32_t& r3) {
    asm volatile("ldmatrix.sync.aligned.m8n8.x4.shared.b16 {%0,%1,%2,%3}, [%4];"
                 : "=r"(r0), "=r"(r1), "=r"(r2), "=r"(r3) : "r"(addr));
}
__device__ __forceinline__ void ldm_x4_t(uint32_t addr, uint32_t& r0, uint32_t& r1,
                                         uint32_t& r2, uint32_t& r3) {
    asm volatile("ldmatrix.sync.aligned.m8n8.x4.trans.shared.b16 {%0,%1,%2,%3}, [%4];"
                 : "=r"(r0), "=r"(r1), "=r"(r2), "=r"(r3) : "r"(addr));
}
__device__ __forceinline__ void mma16816(float* c, uint32_t a0, uint32_t a1,
                                         uint32_t a2, uint32_t a3,
                                         uint32_t b0, uint32_t b1) {
    asm volatile(
        "mma.sync.aligned.m16n8k16.row.col.f32.bf16.bf16.f32 "
        "{%0,%1,%2,%3}, {%4,%5,%6,%7}, {%8,%9}, {%0,%1,%2,%3};"
        : "+f"(c[0]), "+f"(c[1]), "+f"(c[2]), "+f"(c[3])
        : "r"(a0), "r"(a1), "r"(a2), "r"(a3), "r"(b0), "r"(b1));
}
__device__ __forceinline__ void mma16816h(float* c, uint32_t a0, uint32_t a1,
                                          uint32_t a2, uint32_t a3,
                                          uint32_t b0, uint32_t b1) {
    asm volatile(
        "mma.sync.aligned.m16n8k16.row.col.f32.f16.f16.f32 "
        "{%0,%1,%2,%3}, {%4,%5,%6,%7}, {%8,%9}, {%0,%1,%2,%3};"
        : "+f"(c[0]), "+f"(c[1]), "+f"(c[2]), "+f"(c[3])
        : "r"(a0), "r"(a1), "r"(a2), "r"(a3), "r"(b0), "r"(b1));
}

// ===========================================================================
// Prep: A' = [Ahi | Alo | Ahi] along K.  Input [M][1152] fp32.
// ===========================================================================
__global__ void split_A3(const float4* __restrict__ X, __nv_bfloat16* __restrict__ ap,
                         int n4)
{
    int i = blockIdx.x * blockDim.x + threadIdx.x;
    if (i >= n4) return;
    int m  = i / (HID / 4);
    int k  = (i % (HID / 4)) * 4;
    float4 x = X[i];
    __nv_bfloat16 h0 = __float2bfloat16(x.x);
    __nv_bfloat16 h1 = __float2bfloat16(x.y);
    __nv_bfloat16 h2 = __float2bfloat16(x.z);
    __nv_bfloat16 h3 = __float2bfloat16(x.w);
    __nv_bfloat16 l0 = __float2bfloat16(x.x - __bfloat162float(h0));
    __nv_bfloat16 l1 = __float2bfloat16(x.y - __bfloat162float(h1));
    __nv_bfloat16 l2 = __float2bfloat16(x.z - __bfloat162float(h2));
    __nv_bfloat16 l3 = __float2bfloat16(x.w - __bfloat162float(h3));
    __nv_bfloat162 hA(h0, h1), hB(h2, h3), lA(l0, l1), lB(l2, l3);
    __nv_bfloat162* p = (__nv_bfloat162*)(ap + (size_t)m * KP + k);
    p[0] = hA; p[1] = hB;
    *(__nv_bfloat162*)((__nv_bfloat16*)p + HID)         = lA;
    *(__nv_bfloat162*)((__nv_bfloat16*)p + HID + 2)     = lB;
    *(__nv_bfloat162*)((__nv_bfloat16*)p + 2 * HID)     = hA;
    *(__nv_bfloat162*)((__nv_bfloat16*)p + 2 * HID + 2) = hB;
}

// Prep: B'T = [Bhi | Bhi | Blo] along K, transposed.
__global__ void split_T3(const float* __restrict__ W, __nv_bfloat16* __restrict__ bp,
                         int Nd)
{
    __shared__ float tile[32][33];
    int n0 = blockIdx.x * 32, k0 = blockIdx.y * 32;
    int tx = threadIdx.x, ty = threadIdx.y;   // 32 x 8
    for (int i = ty; i < 32; i += 8)
        tile[i][tx] = W[(size_t)(k0 + i) * Nd + n0 + tx];
    __syncthreads();
    for (int i = ty; i < 32; i += 8) {
        float x = tile[tx][i];
        __nv_bfloat16 h = __float2bfloat16(x);
        __nv_bfloat16 l = __float2bfloat16(x - __bfloat162float(h));
        __nv_bfloat16* row = bp + (size_t)(n0 + i) * KP;
        row[k0 + tx]           = h;
        row[HID + k0 + tx]     = h;
        row[2 * HID + k0 + tx] = l;
    }
}

// ===========================================================================
// bf16 mma.sync GEMM (R7 config): 128x128 block, 4 warps (64x64 each), BK=32,
// 3-stage cp.async ring, one __syncthreads per stage, 2 blocks/SM.
// ===========================================================================
#define STAGE_B 20480                 // A (10240) + B (10240) per stage
#define GEMM_SMEM (3 * STAGE_B)       // 61,440 B

__global__ __launch_bounds__(128, 2) void mma_gemm(
    const __nv_bfloat16* __restrict__ Ap, const __nv_bfloat16* __restrict__ Bp,
    const float* __restrict__ bias, float* __restrict__ C, int N)
{
    extern __shared__ __align__(16) char sm[];

    const int t    = threadIdx.x;
    const int wid  = t >> 5;
    const int lane = t & 31;
    const int wm   = wid & 1;
    const int wn   = wid >> 1;
    const int m0   = blockIdx.y * 128;
    const int n0   = blockIdx.x * 128;

    const uint32_t sbase = smem_u32(sm);

    float c[4][8][4];
#pragma unroll
    for (int i = 0; i < 4; i++)
#pragma unroll
        for (int j = 0; j < 8; j++)
#pragma unroll
            for (int q = 0; q < 4; q++) c[i][j][q] = 0.f;

    auto load_stage = [&](int st, int k0) {
        uint32_t sA = sbase + st * STAGE_B;
        uint32_t sB = sA + 10240;
#pragma unroll
        for (int rep = 0; rep < 4; rep++) {
            int cidx = t + rep * 128;
            int row = cidx >> 2;
            int seg = cidx & 3;
            uint32_t soff = (uint32_t)(row * 80 + seg * 16);
            cp_async16(sA + soff, Ap + (size_t)(m0 + row) * KP + k0 + seg * 8);
            cp_async16(sB + soff, Bp + (size_t)(n0 + row) * KP + k0 + seg * 8);
        }
    };

    load_stage(0, 0);  CP_COMMIT();
    load_stage(1, 32); CP_COMMIT();

    const int arow = lane & 15;
    const int acol = (lane >> 4) * 16;
    const int bg   = lane >> 3;
    const int brow = lane & 7;
    const int bnt  = bg >> 1;
    const int bkh  = (bg & 1) * 16;

    int cur = 0;
    for (int kt = 0; kt < NST; kt++) {
        CP_WAIT1();
        __syncthreads();

        int pf = cur + 2; if (pf >= 3) pf -= 3;
        if (kt + 2 < NST) load_stage(pf, (kt + 2) * 32);
        CP_COMMIT();

        const uint32_t sA = sbase + cur * STAGE_B;
        const uint32_t sB = sA + 10240;

#pragma unroll
        for (int kk = 0; kk < 2; kk++) {
            const int kb = kk * 32;
            uint32_t a[4][4];
#pragma unroll
            for (int mt = 0; mt < 4; mt++) {
                uint32_t addr = sA
                    + (uint32_t)((wm * 64 + mt * 16 + arow) * 80 + kb + acol);
                ldm_x4(addr, a[mt][0], a[mt][1], a[mt][2], a[mt][3]);
            }
            uint32_t b[8][2];
#pragma unroll
            for (int p = 0; p < 4; p++) {
                uint32_t addr = sB
                    + (uint32_t)((wn * 64 + p * 16 + bnt * 8 + brow) * 80 + kb + bkh);
                uint32_t r0, r1, r2, r3;
                ldm_x4(addr, r0, r1, r2, r3);
                b[p * 2][0] = r0; b[p * 2][1] = r1;
                b[p * 2 + 1][0] = r2; b[p * 2 + 1][1] = r3;
            }
#pragma unroll
            for (int mt = 0; mt < 4; mt++)
#pragma unroll
                for (int nt = 0; nt < 8; nt++)
                    mma16816(c[mt][nt], a[mt][0], a[mt][1], a[mt][2], a[mt][3],
                             b[nt][0], b[nt][1]);
        }
        cur++; if (cur == 3) cur = 0;
    }

    const int qrow = lane >> 2;
    const int qcol = (lane & 3) * 2;
#pragma unroll
    for (int nt = 0; nt < 8; nt++) {
        int col = n0 + wn * 64 + nt * 8 + qcol;
        float b0 = bias[col], b1 = bias[col + 1];
#pragma unroll
        for (int mt = 0; mt < 4; mt++) {
            int r0 = m0 + wm * 64 + mt * 16 + qrow;
            float2 v0 = make_float2(c[mt][nt][0] + b0, c[mt][nt][1] + b1);
            float2 v1 = make_float2(c[mt][nt][2] + b0, c[mt][nt][3] + b1);
            *(float2*)(C + (size_t)r0 * N + col)       = v0;
            *(float2*)(C + (size_t)(r0 + 8) * N + col) = v1;
        }
    }
}

// ===========================================================================
// RoPE + split for attention operands (Q'/K' bf16x3, V fp16).
// ===========================================================================
__global__ void rope_split(const float* __restrict__ qkv,
                           const float* __restrict__ cosb,
                           const float* __restrict__ sinb,
                           __nv_bfloat16* __restrict__ qp,
                           __nv_bfloat16* __restrict__ kp,
                           __half* __restrict__ vh)
{
    int idx = blockIdx.x * blockDim.x + threadIdx.x;
    if (idx >= S_TOT * NH * 36) return;
    int d   = idx % 36;
    int tmp = idx / 36;
    int h   = tmp % NH;
    int s   = tmp / NH;

    float c  = cosb[s * HD + d];
    float sn = sinb[s * HD + d];
    size_t ib = (size_t)s * H3 + h * HD + d;

    float q0 = qkv[ib], q1 = qkv[ib + 36];
    float rq0 = (q0 * c - q1 * sn) * QSCALE;
    float rq1 = (q1 * c + q0 * sn) * QSCALE;
    float k0 = qkv[ib + HID], k1 = qkv[ib + HID + 36];
    float rk0 = k0 * c - k1 * sn;
    float rk1 = k1 * c + k0 * sn;
    float v0 = qkv[ib + 2 * HID], v1 = qkv[ib + 2 * HID + 36];

    size_t ob = ((size_t)s * NH + h) * QKP;
    __nv_bfloat16 hq0 = __float2bfloat16(rq0);
    __nv_bfloat16 hq1 = __float2bfloat16(rq1);
    __nv_bfloat16 lq0 = __float2bfloat16(rq0 - __bfloat162float(hq0));
    __nv_bfloat16 lq1 = __float2bfloat16(rq1 - __bfloat162float(hq1));
    qp[ob + d]            = hq0;
    qp[ob + d + 36]       = hq1;
    qp[ob + 72 + d]       = lq0;
    qp[ob + 72 + d + 36]  = lq1;
    qp[ob + 144 + d]      = hq0;
    qp[ob + 144 + d + 36] = hq1;

    __nv_bfloat16 hk0 = __float2bfloat16(rk0);
    __nv_bfloat16 hk1 = __float2bfloat16(rk1);
    __nv_bfloat16 lk0 = __float2bfloat16(rk0 - __bfloat162float(hk0));
    __nv_bfloat16 lk1 = __float2bfloat16(rk1 - __bfloat162float(hk1));
    kp[ob + d]            = hk0;
    kp[ob + d + 36]       = hk1;
    kp[ob + 72 + d]       = hk0;
    kp[ob + 72 + d + 36]  = hk1;
    kp[ob + 144 + d]      = lk0;
    kp[ob + 144 + d + 36] = lk1;

    size_t vb = ((size_t)s * NH + h) * 80;
    vh[vb + d]      = __float2half(v0);
    vh[vb + d + 36] = __float2half(v1);

    if (d < 8) {
        __nv_bfloat16 z = __float2bfloat16(0.f);
        qp[ob + 216 + d] = z;
        kp[ob + 216 + d] = z;
        vh[vb + 72 + d]  = __float2half(0.f);
    }
}

// ===========================================================================
// FA2-style mma attention (exp2 domain): BQ=64, 4 warps, 2-stage KV ring,
// 2 blocks/SM. Smem: Q 29,696 + 2 x 40,960 = 111,616 B.
// ===========================================================================
#define SQ_BYTES (64 * 464)
#define SK_BYTES (64 * 464)
#define SV_BYTES (64 * 176)
#define KV_STAGE (SK_BYTES + SV_BYTES)        // 40,960
#define ATT_SMEM (SQ_BYTES + 2 * KV_STAGE)    // 111,616

__global__ __launch_bounds__(128, 2) void attn_mma(
    const __nv_bfloat16* __restrict__ Qp, const __nv_bfloat16* __restrict__ Kp,
    const __half* __restrict__ Vh, __nv_bfloat16* __restrict__ ap)
{
    extern __shared__ char smA[];
    char* sQ  = smA;
    char* sKV = smA + SQ_BYTES;                // 2 stages of [K | V]

    const int t    = threadIdx.x;
    const int lane = t & 31;
    const int wid  = t >> 5;                   // 0..3
    const int qt   = blockIdx.x;               // 0..15
    const int h    = blockIdx.y;               // 0..15
    const int seg  = blockIdx.z;               // 0..7
    const int sbase = seg * LSEG;
    const int qbase = sbase + qt * 64;
    const int q0    = wid * 16;

    auto load_q = [&]() {
        for (int c = t; c < 64 * 28; c += 128) {
            int row = c / 28, ch = c % 28;
            cp_async16(smem_u32(sQ + row * 464 + ch * 16),
                       Qp + ((size_t)(qbase + row) * NH + h) * QKP + ch * 8);
        }
    };
    auto load_kv = [&](int st, int kb) {
        char* dk = sKV + st * KV_STAGE;
        char* dv = dk + SK_BYTES;
        for (int c = t; c < 64 * 28 + 64 * 10; c += 128) {
            if (c < 1792) {
                int row = c / 28, ch = c % 28;
                cp_async16(smem_u32(dk + row * 464 + ch * 16),
                           Kp + ((size_t)(sbase + kb + row) * NH + h) * QKP + ch * 8);
            } else {
                int c2 = c - 1792;
                int row = c2 / 10, ch = c2 % 10;
                cp_async16(smem_u32(dv + row * 176 + ch * 16),
                           Vh + ((size_t)(sbase + kb + row) * NH + h) * 80 + ch * 8);
            }
        }
    };

    load_q(); load_kv(0, 0); CP_COMMIT();
    load_kv(1, 64); CP_COMMIT();

    uint32_t qf[14][4];
    float o[10][4];
#pragma unroll
    for (int j = 0; j < 10; j++)
#pragma unroll
        for (int q = 0; q < 4; q++) o[j][q] = 0.f;
    float m0v = -1e30f, m1v = -1e30f, l0v = 0.f, l1v = 0.f;

    const int qlrow = lane % 16;
    const int qlcol = (lane / 16) * 16;
    const int bkey  = (lane / 16) * 8 + (lane % 8);
    const int bkoff = ((lane / 8) & 1) * 16;
    const int vkey  = ((lane / 8) & 1) * 8 + (lane % 8);
    const int vdoff = (lane / 16) * 16;

    for (int kt = 0; kt < 16; kt++) {
        if (kt == 15) { CP_WAIT0(); } else { CP_WAIT1(); }
        __syncthreads();

        if (kt == 0) {
#pragma unroll
            for (int kk = 0; kk < 14; kk++) {
                uint32_t addr = smem_u32(sQ + (q0 + qlrow) * 464 + kk * 32 + qlcol);
                ldm_x4(addr, qf[kk][0], qf[kk][1], qf[kk][2], qf[kk][3]);
            }
        }

        const char* bk = sKV + (kt & 1) * KV_STAGE;
        const char* bv = bk + SK_BYTES;

        float s[8][4];
#pragma unroll
        for (int j = 0; j < 8; j++)
#pragma unroll
            for (int q = 0; q < 4; q++) s[j][q] = 0.f;

#pragma unroll
        for (int kk = 0; kk < 14; kk++) {
#pragma unroll
            for (int pr = 0; pr < 4; pr++) {
                uint32_t addr = smem_u32(bk + (pr * 16 + bkey) * 464 + kk * 32 + bkoff);
                uint32_t r0, r1, r2, r3;
                ldm_x4(addr, r0, r1, r2, r3);
                mma16816(s[pr * 2],     qf[kk][0], qf[kk][1], qf[kk][2], qf[kk][3], r0, r1);
                mma16816(s[pr * 2 + 1], qf[kk][0], qf[kk][1], qf[kk][2], qf[kk][3], r2, r3);
            }
        }

        float rx0 = -1e30f, rx1 = -1e30f;
#pragma unroll
        for (int j = 0; j < 8; j++) {
            rx0 = fmaxf(rx0, fmaxf(s[j][0], s[j][1]));
            rx1 = fmaxf(rx1, fmaxf(s[j][2], s[j][3]));
        }
        rx0 = fmaxf(rx0, __shfl_xor_sync(0xffffffffu, rx0, 1));
        rx0 = fmaxf(rx0, __shfl_xor_sync(0xffffffffu, rx0, 2));
        rx1 = fmaxf(rx1, __shfl_xor_sync(0xffffffffu, rx1, 1));
        rx1 = fmaxf(rx1, __shfl_xor_sync(0xffffffffu, rx1, 2));

        float mn0 = fmaxf(m0v, rx0), mn1 = fmaxf(m1v, rx1);
        float a0 = exp2f(m0v - mn0), a1 = exp2f(m1v - mn1);
        m0v = mn0; m1v = mn1;

        float sum0 = 0.f, sum1 = 0.f;
#pragma unroll
        for (int j = 0; j < 8; j++) {
            s[j][0] = exp2f(s[j][0] - mn0);
            s[j][1] = exp2f(s[j][1] - mn0);
            s[j][2] = exp2f(s[j][2] - mn1);
            s[j][3] = exp2f(s[j][3] - mn1);
            sum0 += s[j][0] + s[j][1];
            sum1 += s[j][2] + s[j][3];
        }
        sum0 += __shfl_xor_sync(0xffffffffu, sum0, 1);
        sum0 += __shfl_xor_sync(0xffffffffu, sum0, 2);
        sum1 += __shfl_xor_sync(0xffffffffu, sum1, 1);
        sum1 += __shfl_xor_sync(0xffffffffu, sum1, 2);
        l0v = l0v * a0 + sum0;
        l1v = l1v * a1 + sum1;

#pragma unroll
        for (int j = 0; j < 10; j++) {
            o[j][0] *= a0; o[j][1] *= a0;
            o[j][2] *= a1; o[j][3] *= a1;
        }

        uint32_t pa[4][4];
#pragma unroll
        for (int kk2 = 0; kk2 < 4; kk2++) {
            int j = 2 * kk2;
            __half2 h0 = __floats2half2_rn(s[j][0],     s[j][1]);
            __half2 h1 = __floats2half2_rn(s[j][2],     s[j][3]);
            __half2 h2 = __floats2half2_rn(s[j + 1][0], s[j + 1][1]);
            __half2 h3 = __floats2half2_rn(s[j + 1][2], s[j + 1][3]);
            pa[kk2][0] = *(uint32_t*)&h0;
            pa[kk2][1] = *(uint32_t*)&h1;
            pa[kk2][2] = *(uint32_t*)&h2;
            pa[kk2][3] = *(uint32_t*)&h3;
        }

#pragma unroll
        for (int kk2 = 0; kk2 < 4; kk2++) {
#pragma unroll
            for (int vp = 0; vp < 5; vp++) {
                uint32_t addr = smem_u32(bv + (kk2 * 16 + vkey) * 176 + vp * 32 + vdoff);
                uint32_t r0, r1, r2, r3;
                ldm_x4_t(addr, r0, r1, r2, r3);
                mma16816h(o[vp * 2],     pa[kk2][0], pa[kk2][1], pa[kk2][2], pa[kk2][3], r0, r1);
                mma16816h(o[vp * 2 + 1], pa[kk2][0], pa[kk2][1], pa[kk2][2], pa[kk2][3], r2, r3);
            }
        }

        __syncthreads();
        if (kt + 2 < 16) {
            load_kv(kt & 1, (kt + 2) * 64);
            CP_COMMIT();
        }
    }

    // ---- store bf16x3 split directly into A' rows (dims 0..71 only) ----
    float inv0 = 1.f / l0v, inv1 = 1.f / l1v;
    int r_lo = qbase + q0 + lane / 4;
    int r_hi = r_lo + 8;
#pragma unroll
    for (int j = 0; j < 9; j++) {
        int col = h * HD + j * 8 + (lane & 3) * 2;
        float x0 = o[j][0] * inv0, x1 = o[j][1] * inv0;
        float x2 = o[j][2] * inv1, x3 = o[j][3] * inv1;

        __nv_bfloat16 hx0 = __float2bfloat16(x0);
        __nv_bfloat16 hx1 = __float2bfloat16(x1);
        __nv_bfloat162 hp0(hx0, hx1);
        __nv_bfloat162 lp0(__float2bfloat16(x0 - __bfloat162float(hx0)),
                           __float2bfloat16(x1 - __bfloat162float(hx1)));
        __nv_bfloat16* row0 = ap + (size_t)r_lo * KP + col;
        *(__nv_bfloat162*)(row0)           = hp0;
        *(__nv_bfloat162*)(row0 + HID)     = lp0;
        *(__nv_bfloat162*)(row0 + 2 * HID) = hp0;

        __nv_bfloat16 hx2 = __float2bfloat16(x2);
        __nv_bfloat16 hx3 = __float2bfloat16(x3);
        __nv_bfloat162 hp1(hx2, hx3);
        __nv_bfloat162 lp1(__float2bfloat16(x2 - __bfloat162float(hx2)),
                           __float2bfloat16(x3 - __bfloat162float(hx3)));
        __nv_bfloat16* row1 = ap + (size_t)r_hi * KP + col;
        *(__nv_bfloat162*)(row1)           = hp1;
        *(__nv_bfloat162*)(row1 + HID)     = lp1;
        *(__nv_bfloat162*)(row1 + 2 * HID) = hp1;
    }
}

// ===========================================================================
// Launch
// ===========================================================================
extern "C" void kernel_launch(void* const* d_in, const int* in_sizes, int n_in,
                              void* d_out, int out_size)
{
    const float* hidden = (const float*)d_in[0];
    const float* cosb   = (const float*)d_in[1];
    const float* sinb   = (const float*)d_in[2];
    const float* Wqkv   = (const float*)d_in[3];
    const float* bqkv   = (const float*)d_in[4];
    const float* Wout   = (const float*)d_in[5];
    const float* bout   = (const float*)d_in[6];
    float* out = (float*)d_out;

    float *qkv;
    __nv_bfloat16 *ap, *wqp, *wop, *qp, *kp2;
    __half *vh;
    cudaGetSymbolAddress((void**)&qkv, g_qkv);
    cudaGetSymbolAddress((void**)&ap, g_ap);
    cudaGetSymbolAddress((void**)&wqp, g_wqp);
    cudaGetSymbolAddress((void**)&wop, g_wop);
    cudaGetSymbolAddress((void**)&qp, g_qp);
    cudaGetSymbolAddress((void**)&kp2, g_kp2);
    cudaGetSymbolAddress((void**)&vh, g_vh);

    cudaFuncSetAttribute(mma_gemm, cudaFuncAttributeMaxDynamicSharedMemorySize, GEMM_SMEM);
    cudaFuncSetAttribute(attn_mma, cudaFuncAttributeMaxDynamicSharedMemorySize, ATT_SMEM);

    int n4 = S_TOT * HID / 4;

    // Prep: expanded bf16x3 operands
    split_A3<<<(n4 + 255) / 256, 256>>>((const float4*)hidden, ap, n4);
    dim3 tb(32, 8);
    split_T3<<<dim3(H3 / 32, HID / 32), tb>>>(Wqkv, wqp, H3);
    split_T3<<<dim3(HID / 32, HID / 32), tb>>>(Wout, wop, HID);

    // 1) QKV projection + bias (tensor cores)
    mma_gemm<<<dim3(H3 / 128, S_TOT / 128), 128, GEMM_SMEM>>>(ap, wqp, bqkv, qkv, H3);

    // 2) RoPE + attention-operand split
    int nrope = S_TOT * NH * 36;
    rope_split<<<(nrope + 255) / 256, 256>>>(qkv, cosb, sinb, qp, kp2, vh);

    // 3) Attention (tensor cores, 2 blocks/SM) -> writes bf16x3 ctx into g_ap
    dim3 ga(16, NH, NSEG);
    attn_mma<<<ga, 128, ATT_SMEM>>>(qp, kp2, vh, ap);

    // 4) Output projection + bias (tensor cores)
    mma_gemm<<<dim3(HID / 128, S_TOT / 128), 128, GEMM_SMEM>>>(ap, wop, bout, out, HID);
}

// round 13
// speedup vs baseline: 1.2940x; 1.2940x over previous
#include <cuda_runtime.h>
#include <cuda_bf16.h>
#include <cuda_fp16.h>
#include <cstdint>
#include <cstddef>

// Problem constants
#define S_TOT  8192
#define HID    1152
#define NH     16
#define HD     72
#define NSEG   8
#define LSEG   1024
#define H3     3456
#define ATT_SCALE 0.11785113019775793f   // 72^-0.5
#define LOG2E     1.4426950408889634f
#define QSCALE    (ATT_SCALE * LOG2E)    // softmax in exp2 domain
#define KP2    2304                      // fp16 split-2 K' = 2*1152
#define NST2   (KP2 / 32)                // 72 k-stages of 32
#define QKP    224                       // attention Q'/K' depth (bf16x3): 216 pad 224

// Scratch (allocation-free rule: __device__ globals)
__device__ float g_qkv[(size_t)S_TOT * H3];              // 113 MB
__device__ __half g_ap[(size_t)S_TOT * KP2];             // A' [M][2K] fp16 [hi|lo]
__device__ __half g_wqp[(size_t)H3 * KP2];               // Wqkv'T fp16 [hi|hi]
__device__ __half g_wop[(size_t)HID * KP2];              // Wout'T fp16 [hi|hi]
__device__ __nv_bfloat16 g_qp[(size_t)S_TOT * NH * QKP]; // Q' bf16x3
__device__ __nv_bfloat16 g_kp2[(size_t)S_TOT * NH * QKP];// K' bf16x3
__device__ __half        g_vh[(size_t)S_TOT * NH * 80];  // V fp16 [s][h][80]

// ===========================================================================
// PTX helpers (portable sm_80-class only — no tcgen05 on compute_103)
// ===========================================================================
__device__ __forceinline__ uint32_t smem_u32(const void* p) {
    uint32_t a;
    asm("{ .reg .u64 t; cvta.to.shared.u64 t, %1; cvt.u32.u64 %0, t; }"
        : "=r"(a) : "l"(p));
    return a;
}
__device__ __forceinline__ void cp_async16(uint32_t s, const void* g) {
    asm volatile("cp.async.cg.shared.global [%0], [%1], 16;" :: "r"(s), "l"(g));
}
#define CP_COMMIT() asm volatile("cp.async.commit_group;" ::: "memory")
#define CP_WAIT0()  asm volatile("cp.async.wait_group 0;" ::: "memory")
#define CP_WAIT1()  asm volatile("cp.async.wait_group 1;" ::: "memory")

__device__ __forceinline__ void ldm_x4(uint32_t addr, uint32_t& r0, uint32_t& r1,
                                       uint32_t& r2, uint32_t& r3) {
    asm volatile("ldmatrix.sync.aligned.m8n8.x4.shared.b16 {%0,%1,%2,%3}, [%4];"
                 : "=r"(r0), "=r"(r1), "=r"(r2), "=r"(r3) : "r"(addr));
}
__device__ __forceinline__ void ldm_x4_t(uint32_t addr, uint32_t& r0, uint32_t& r1,
                                         uint32_t& r2, uint32_t& r3) {
    asm volatile("ldmatrix.sync.aligned.m8n8.x4.trans.shared.b16 {%0,%1,%2,%3}, [%4];"
                 : "=r"(r0), "=r"(r1), "=r"(r2), "=r"(r3) : "r"(addr));
}
__device__ __forceinline__ void mma16816(float* c, uint32_t a0, uint32_t a1,
                                         uint32_t a2, uint32_t a3,
                                         uint32_t b0, uint32_t b1) {
    asm volatile(
        "mma.sync.aligned.m16n8k16.row.col.f32.bf16.bf16.f32 "
        "{%0,%1,%2,%3}, {%4,%5,%6,%7}, {%8,%9}, {%0,%1,%2,%3};"
        : "+f"(c[0]), "+f"(c[1]), "+f"(c[2]), "+f"(c[3])
        : "r"(a0), "r"(a1), "r"(a2), "r"(a3), "r"(b0), "r"(b1));
}
__device__ __forceinline__ void mma16816h(float* c, uint32_t a0, uint32_t a1,
                                          uint32_t a2, uint32_t a3,
                                          uint32_t b0, uint32_t b1) {
    asm volatile(
        "mma.sync.aligned.m16n8k16.row.col.f32.f16.f16.f32 "
        "{%0,%1,%2,%3}, {%4,%5,%6,%7}, {%8,%9}, {%0,%1,%2,%3};"
        : "+f"(c[0]), "+f"(c[1]), "+f"(c[2]), "+f"(c[3])
        : "r"(a0), "r"(a1), "r"(a2), "r"(a3), "r"(b0), "r"(b1));
}

// ===========================================================================
// Prep: A' = [Ahi | Alo] fp16 along K.  Input [M][1152] fp32.
// ===========================================================================
__global__ void split_A2(const float4* __restrict__ X, __half* __restrict__ ap,
                         int n4)
{
    int i = blockIdx.x * blockDim.x + threadIdx.x;
    if (i >= n4) return;
    int m  = i / (HID / 4);
    int k  = (i % (HID / 4)) * 4;
    float4 x = X[i];
    __half h0 = __float2half(x.x);
    __half h1 = __float2half(x.y);
    __half h2 = __float2half(x.z);
    __half h3 = __float2half(x.w);
    __half l0 = __float2half(x.x - __half2float(h0));
    __half l1 = __float2half(x.y - __half2float(h1));
    __half l2 = __float2half(x.z - __half2float(h2));
    __half l3 = __float2half(x.w - __half2float(h3));
    __half* p = ap + (size_t)m * KP2 + k;
    *(__half2*)(p)           = __half2(h0, h1);
    *(__half2*)(p + 2)       = __half2(h2, h3);
    *(__half2*)(p + HID)     = __half2(l0, l1);
    *(__half2*)(p + HID + 2) = __half2(l2, l3);
}

// Prep: B'T = [Bhi | Bhi] fp16 along K, transposed.
__global__ void split_T2(const float* __restrict__ W, __half* __restrict__ bp,
                         int Nd)
{
    __shared__ float tile[32][33];
    int n0 = blockIdx.x * 32, k0 = blockIdx.y * 32;
    int tx = threadIdx.x, ty = threadIdx.y;   // 32 x 8
    for (int i = ty; i < 32; i += 8)
        tile[i][tx] = W[(size_t)(k0 + i) * Nd + n0 + tx];
    __syncthreads();
    for (int i = ty; i < 32; i += 8) {
        __half h = __float2half(tile[tx][i]);
        __half* row = bp + (size_t)(n0 + i) * KP2;
        row[k0 + tx]       = h;
        row[HID + k0 + tx] = h;
    }
}

// ===========================================================================
// fp16 mma.sync GEMM (R7 structure): C[M,N] = A'[M,KP2] @ B'T[N,KP2] + bias[N]
// 128x128 block, 4 warps (64x64 each), BK=32, 3-stage ring, 2 blocks/SM.
// ===========================================================================
#define STAGE_B 20480                 // A (10240) + B (10240) per stage
#define GEMM_SMEM (3 * STAGE_B)       // 61,440 B

__global__ __launch_bounds__(128, 2) void mma_gemm(
    const __half* __restrict__ Ap, const __half* __restrict__ Bp,
    const float* __restrict__ bias, float* __restrict__ C, int N)
{
    extern __shared__ __align__(16) char sm[];

    const int t    = threadIdx.x;
    const int wid  = t >> 5;
    const int lane = t & 31;
    const int wm   = wid & 1;
    const int wn   = wid >> 1;
    const int m0   = blockIdx.y * 128;
    const int n0   = blockIdx.x * 128;

    const uint32_t sbase = smem_u32(sm);

    float c[4][8][4];
#pragma unroll
    for (int i = 0; i < 4; i++)
#pragma unroll
        for (int j = 0; j < 8; j++)
#pragma unroll
            for (int q = 0; q < 4; q++) c[i][j][q] = 0.f;

    auto load_stage = [&](int st, int k0) {
        uint32_t sA = sbase + st * STAGE_B;
        uint32_t sB = sA + 10240;
#pragma unroll
        for (int rep = 0; rep < 4; rep++) {
            int cidx = t + rep * 128;
            int row = cidx >> 2;
            int seg = cidx & 3;
            uint32_t soff = (uint32_t)(row * 80 + seg * 16);
            cp_async16(sA + soff, Ap + (size_t)(m0 + row) * KP2 + k0 + seg * 8);
            cp_async16(sB + soff, Bp + (size_t)(n0 + row) * KP2 + k0 + seg * 8);
        }
    };

    load_stage(0, 0);  CP_COMMIT();
    load_stage(1, 32); CP_COMMIT();

    const int arow = lane & 15;
    const int acol = (lane >> 4) * 16;
    const int bg   = lane >> 3;
    const int brow = lane & 7;
    const int bnt  = bg >> 1;
    const int bkh  = (bg & 1) * 16;

    int cur = 0;
    for (int kt = 0; kt < NST2; kt++) {
        CP_WAIT1();
        __syncthreads();

        int pf = cur + 2; if (pf >= 3) pf -= 3;
        if (kt + 2 < NST2) load_stage(pf, (kt + 2) * 32);
        CP_COMMIT();

        const uint32_t sA = sbase + cur * STAGE_B;
        const uint32_t sB = sA + 10240;

#pragma unroll
        for (int kk = 0; kk < 2; kk++) {
            const int kb = kk * 32;
            uint32_t a[4][4];
#pragma unroll
            for (int mt = 0; mt < 4; mt++) {
                uint32_t addr = sA
                    + (uint32_t)((wm * 64 + mt * 16 + arow) * 80 + kb + acol);
                ldm_x4(addr, a[mt][0], a[mt][1], a[mt][2], a[mt][3]);
            }
            uint32_t b[8][2];
#pragma unroll
            for (int p = 0; p < 4; p++) {
                uint32_t addr = sB
                    + (uint32_t)((wn * 64 + p * 16 + bnt * 8 + brow) * 80 + kb + bkh);
                uint32_t r0, r1, r2, r3;
                ldm_x4(addr, r0, r1, r2, r3);
                b[p * 2][0] = r0; b[p * 2][1] = r1;
                b[p * 2 + 1][0] = r2; b[p * 2 + 1][1] = r3;
            }
#pragma unroll
            for (int mt = 0; mt < 4; mt++)
#pragma unroll
                for (int nt = 0; nt < 8; nt++)
                    mma16816h(c[mt][nt], a[mt][0], a[mt][1], a[mt][2], a[mt][3],
                              b[nt][0], b[nt][1]);
        }
        cur++; if (cur == 3) cur = 0;
    }

    const int qrow = lane >> 2;
    const int qcol = (lane & 3) * 2;
#pragma unroll
    for (int nt = 0; nt < 8; nt++) {
        int col = n0 + wn * 64 + nt * 8 + qcol;
        float b0 = bias[col], b1 = bias[col + 1];
#pragma unroll
        for (int mt = 0; mt < 4; mt++) {
            int r0 = m0 + wm * 64 + mt * 16 + qrow;
            float2 v0 = make_float2(c[mt][nt][0] + b0, c[mt][nt][1] + b1);
            float2 v1 = make_float2(c[mt][nt][2] + b0, c[mt][nt][3] + b1);
            *(float2*)(C + (size_t)r0 * N + col)       = v0;
            *(float2*)(C + (size_t)(r0 + 8) * N + col) = v1;
        }
    }
}

// ===========================================================================
// RoPE + split for attention operands (Q'/K' bf16x3, V fp16).
// ===========================================================================
__global__ void rope_split(const float* __restrict__ qkv,
                           const float* __restrict__ cosb,
                           const float* __restrict__ sinb,
                           __nv_bfloat16* __restrict__ qp,
                           __nv_bfloat16* __restrict__ kp,
                           __half* __restrict__ vh)
{
    int idx = blockIdx.x * blockDim.x + threadIdx.x;
    if (idx >= S_TOT * NH * 36) return;
    int d   = idx % 36;
    int tmp = idx / 36;
    int h   = tmp % NH;
    int s   = tmp / NH;

    float c  = cosb[s * HD + d];
    float sn = sinb[s * HD + d];
    size_t ib = (size_t)s * H3 + h * HD + d;

    float q0 = qkv[ib], q1 = qkv[ib + 36];
    float rq0 = (q0 * c - q1 * sn) * QSCALE;
    float rq1 = (q1 * c + q0 * sn) * QSCALE;
    float k0 = qkv[ib + HID], k1 = qkv[ib + HID + 36];
    float rk0 = k0 * c - k1 * sn;
    float rk1 = k1 * c + k0 * sn;
    float v0 = qkv[ib + 2 * HID], v1 = qkv[ib + 2 * HID + 36];

    size_t ob = ((size_t)s * NH + h) * QKP;
    __nv_bfloat16 hq0 = __float2bfloat16(rq0);
    __nv_bfloat16 hq1 = __float2bfloat16(rq1);
    __nv_bfloat16 lq0 = __float2bfloat16(rq0 - __bfloat162float(hq0));
    __nv_bfloat16 lq1 = __float2bfloat16(rq1 - __bfloat162float(hq1));
    qp[ob + d]            = hq0;
    qp[ob + d + 36]       = hq1;
    qp[ob + 72 + d]       = lq0;
    qp[ob + 72 + d + 36]  = lq1;
    qp[ob + 144 + d]      = hq0;
    qp[ob + 144 + d + 36] = hq1;

    __nv_bfloat16 hk0 = __float2bfloat16(rk0);
    __nv_bfloat16 hk1 = __float2bfloat16(rk1);
    __nv_bfloat16 lk0 = __float2bfloat16(rk0 - __bfloat162float(hk0));
    __nv_bfloat16 lk1 = __float2bfloat16(rk1 - __bfloat162float(hk1));
    kp[ob + d]            = hk0;
    kp[ob + d + 36]       = hk1;
    kp[ob + 72 + d]       = hk0;
    kp[ob + 72 + d + 36]  = hk1;
    kp[ob + 144 + d]      = lk0;
    kp[ob + 144 + d + 36] = lk1;

    size_t vb = ((size_t)s * NH + h) * 80;
    vh[vb + d]      = __float2half(v0);
    vh[vb + d + 36] = __float2half(v1);

    if (d < 8) {
        __nv_bfloat16 z = __float2bfloat16(0.f);
        qp[ob + 216 + d] = z;
        kp[ob + 216 + d] = z;
        vh[vb + 72 + d]  = __float2half(0.f);
    }
}

// ===========================================================================
// FA2-style mma attention (R11 config): BQ=128, 256 thr, 3-stage KV ring.
// Epilogue writes fp16 [hi|lo] ctx directly into g_ap.
// ===========================================================================
#define SQ_BYTES (128 * 464)
#define SK_BYTES (64 * 464)
#define SV_BYTES (64 * 176)
#define KV_STAGE (SK_BYTES + SV_BYTES)        // 40,960
#define ATT_SMEM (SQ_BYTES + 3 * KV_STAGE)    // 182,272

__global__ __launch_bounds__(256, 1) void attn_mma(
    const __nv_bfloat16* __restrict__ Qp, const __nv_bfloat16* __restrict__ Kp,
    const __half* __restrict__ Vh, __half* __restrict__ ap)
{
    extern __shared__ char smA[];
    char* sQ  = smA;
    char* sKV = smA + SQ_BYTES;                // 3 stages of [K | V]

    const int t    = threadIdx.x;
    const int lane = t & 31;
    const int wid  = t >> 5;
    const int qt   = blockIdx.x;     // 0..7
    const int h    = blockIdx.y;     // 0..15
    const int seg  = blockIdx.z;     // 0..7
    const int sbase = seg * LSEG;
    const int qbase = sbase + qt * 128;
    const int q0    = wid * 16;

    auto load_q = [&]() {
        for (int c = t; c < 128 * 28; c += 256) {
            int row = c / 28, ch = c % 28;
            cp_async16(smem_u32(sQ + row * 464 + ch * 16),
                       Qp + ((size_t)(qbase + row) * NH + h) * QKP + ch * 8);
        }
    };
    auto load_kv = [&](int st, int kb) {
        char* dk = sKV + st * KV_STAGE;
        char* dv = dk + SK_BYTES;
        for (int c = t; c < 64 * 28 + 64 * 10; c += 256) {
            if (c < 1792) {
                int row = c / 28, ch = c % 28;
                cp_async16(smem_u32(dk + row * 464 + ch * 16),
                           Kp + ((size_t)(sbase + kb + row) * NH + h) * QKP + ch * 8);
            } else {
                int c2 = c - 1792;
                int row = c2 / 10, ch = c2 % 10;
                cp_async16(smem_u32(dv + row * 176 + ch * 16),
                           Vh + ((size_t)(sbase + kb + row) * NH + h) * 80 + ch * 8);
            }
        }
    };

    load_q(); load_kv(0, 0); CP_COMMIT();
    load_kv(1, 64); CP_COMMIT();

    uint32_t qf[14][4];
    float o[10][4];
#pragma unroll
    for (int j = 0; j < 10; j++)
#pragma unroll
        for (int q = 0; q < 4; q++) o[j][q] = 0.f;
    float m0v = -1e30f, m1v = -1e30f, l0v = 0.f, l1v = 0.f;

    const int qlrow = lane % 16;
    const int qlcol = (lane / 16) * 16;
    const int bkey  = (lane / 16) * 8 + (lane % 8);
    const int bkoff = ((lane / 8) & 1) * 16;
    const int vkey  = ((lane / 8) & 1) * 8 + (lane % 8);
    const int vdoff = (lane / 16) * 16;

    int cur = 0;
    for (int kt = 0; kt < 16; kt++) {
        CP_WAIT1();
        __syncthreads();

        int pf = cur + 2; if (pf >= 3) pf -= 3;
        if (kt + 2 < 16) load_kv(pf, (kt + 2) * 64);
        CP_COMMIT();

        if (kt == 0) {
#pragma unroll
            for (int kk = 0; kk < 14; kk++) {
                uint32_t addr = smem_u32(sQ + (q0 + qlrow) * 464 + kk * 32 + qlcol);
                ldm_x4(addr, qf[kk][0], qf[kk][1], qf[kk][2], qf[kk][3]);
            }
        }

        const char* bk = sKV + cur * KV_STAGE;
        const char* bv = bk + SK_BYTES;

        float s[8][4];
#pragma unroll
        for (int j = 0; j < 8; j++)
#pragma unroll
            for (int q = 0; q < 4; q++) s[j][q] = 0.f;

#pragma unroll
        for (int kk = 0; kk < 14; kk++) {
#pragma unroll
            for (int pr = 0; pr < 4; pr++) {
                uint32_t addr = smem_u32(bk + (pr * 16 + bkey) * 464 + kk * 32 + bkoff);
                uint32_t r0, r1, r2, r3;
                ldm_x4(addr, r0, r1, r2, r3);
                mma16816(s[pr * 2],     qf[kk][0], qf[kk][1], qf[kk][2], qf[kk][3], r0, r1);
                mma16816(s[pr * 2 + 1], qf[kk][0], qf[kk][1], qf[kk][2], qf[kk][3], r2, r3);
            }
        }

        float rx0 = -1e30f, rx1 = -1e30f;
#pragma unroll
        for (int j = 0; j < 8; j++) {
            rx0 = fmaxf(rx0, fmaxf(s[j][0], s[j][1]));
            rx1 = fmaxf(rx1, fmaxf(s[j][2], s[j][3]));
        }
        rx0 = fmaxf(rx0, __shfl_xor_sync(0xffffffffu, rx0, 1));
        rx0 = fmaxf(rx0, __shfl_xor_sync(0xffffffffu, rx0, 2));
        rx1 = fmaxf(rx1, __shfl_xor_sync(0xffffffffu, rx1, 1));
        rx1 = fmaxf(rx1, __shfl_xor_sync(0xffffffffu, rx1, 2));

        float mn0 = fmaxf(m0v, rx0), mn1 = fmaxf(m1v, rx1);
        float a0 = exp2f(m0v - mn0), a1 = exp2f(m1v - mn1);
        m0v = mn0; m1v = mn1;

        float sum0 = 0.f, sum1 = 0.f;
#pragma unroll
        for (int j = 0; j < 8; j++) {
            s[j][0] = exp2f(s[j][0] - mn0);
            s[j][1] = exp2f(s[j][1] - mn0);
            s[j][2] = exp2f(s[j][2] - mn1);
            s[j][3] = exp2f(s[j][3] - mn1);
            sum0 += s[j][0] + s[j][1];
            sum1 += s[j][2] + s[j][3];
        }
        sum0 += __shfl_xor_sync(0xffffffffu, sum0, 1);
        sum0 += __shfl_xor_sync(0xffffffffu, sum0, 2);
        sum1 += __shfl_xor_sync(0xffffffffu, sum1, 1);
        sum1 += __shfl_xor_sync(0xffffffffu, sum1, 2);
        l0v = l0v * a0 + sum0;
        l1v = l1v * a1 + sum1;

#pragma unroll
        for (int j = 0; j < 10; j++) {
            o[j][0] *= a0; o[j][1] *= a0;
            o[j][2] *= a1; o[j][3] *= a1;
        }

        uint32_t pa[4][4];
#pragma unroll
        for (int kk2 = 0; kk2 < 4; kk2++) {
            int j = 2 * kk2;
            __half2 h0 = __floats2half2_rn(s[j][0],     s[j][1]);
            __half2 h1 = __floats2half2_rn(s[j][2],     s[j][3]);
            __half2 h2 = __floats2half2_rn(s[j + 1][0], s[j + 1][1]);
            __half2 h3 = __floats2half2_rn(s[j + 1][2], s[j + 1][3]);
            pa[kk2][0] = *(uint32_t*)&h0;
            pa[kk2][1] = *(uint32_t*)&h1;
            pa[kk2][2] = *(uint32_t*)&h2;
            pa[kk2][3] = *(uint32_t*)&h3;
        }

#pragma unroll
        for (int kk2 = 0; kk2 < 4; kk2++) {
#pragma unroll
            for (int vp = 0; vp < 5; vp++) {
                uint32_t addr = smem_u32(bv + (kk2 * 16 + vkey) * 176 + vp * 32 + vdoff);
                uint32_t r0, r1, r2, r3;
                ldm_x4_t(addr, r0, r1, r2, r3);
                mma16816h(o[vp * 2],     pa[kk2][0], pa[kk2][1], pa[kk2][2], pa[kk2][3], r0, r1);
                mma16816h(o[vp * 2 + 1], pa[kk2][0], pa[kk2][1], pa[kk2][2], pa[kk2][3], r2, r3);
            }
        }

        cur++; if (cur == 3) cur = 0;
    }

    // ---- store fp16 [hi|lo] directly into A' rows (dims 0..71 only) ----
    float inv0 = 1.f / l0v, inv1 = 1.f / l1v;
    int r_lo = qbase + q0 + lane / 4;
    int r_hi = r_lo + 8;
#pragma unroll
    for (int j = 0; j < 9; j++) {
        int col = h * HD + j * 8 + (lane & 3) * 2;
        float x0 = o[j][0] * inv0, x1 = o[j][1] * inv0;
        float x2 = o[j][2] * inv1, x3 = o[j][3] * inv1;

        __half hx0 = __float2half(x0);
        __half hx1 = __float2half(x1);
        __half lx0 = __float2half(x0 - __half2float(hx0));
        __half lx1 = __float2half(x1 - __half2float(hx1));
        __half* row0 = ap + (size_t)r_lo * KP2 + col;
        *(__half2*)(row0)       = __half2(hx0, hx1);
        *(__half2*)(row0 + HID) = __half2(lx0, lx1);

        __half hx2 = __float2half(x2);
        __half hx3 = __float2half(x3);
        __half lx2 = __float2half(x2 - __half2float(hx2));
        __half lx3 = __float2half(x3 - __half2float(hx3));
        __half* row1 = ap + (size_t)r_hi * KP2 + col;
        *(__half2*)(row1)       = __half2(hx2, hx3);
        *(__half2*)(row1 + HID) = __half2(lx2, lx3);
    }
}

// ===========================================================================
// Launch
// ===========================================================================
extern "C" void kernel_launch(void* const* d_in, const int* in_sizes, int n_in,
                              void* d_out, int out_size)
{
    const float* hidden = (const float*)d_in[0];
    const float* cosb   = (const float*)d_in[1];
    const float* sinb   = (const float*)d_in[2];
    const float* Wqkv   = (const float*)d_in[3];
    const float* bqkv   = (const float*)d_in[4];
    const float* Wout   = (const float*)d_in[5];
    const float* bout   = (const float*)d_in[6];
    float* out = (float*)d_out;

    float *qkv;
    __half *ap, *wqp, *wop, *vh;
    __nv_bfloat16 *qp, *kp2;
    cudaGetSymbolAddress((void**)&qkv, g_qkv);
    cudaGetSymbolAddress((void**)&ap, g_ap);
    cudaGetSymbolAddress((void**)&wqp, g_wqp);
    cudaGetSymbolAddress((void**)&wop, g_wop);
    cudaGetSymbolAddress((void**)&qp, g_qp);
    cudaGetSymbolAddress((void**)&kp2, g_kp2);
    cudaGetSymbolAddress((void**)&vh, g_vh);

    cudaFuncSetAttribute(mma_gemm, cudaFuncAttributeMaxDynamicSharedMemorySize, GEMM_SMEM);
    cudaFuncSetAttribute(attn_mma, cudaFuncAttributeMaxDynamicSharedMemorySize, ATT_SMEM);

    int n4 = S_TOT * HID / 4;

    // Prep: fp16 split-2 operands
    split_A2<<<(n4 + 255) / 256, 256>>>((const float4*)hidden, ap, n4);
    dim3 tb(32, 8);
    split_T2<<<dim3(H3 / 32, HID / 32), tb>>>(Wqkv, wqp, H3);
    split_T2<<<dim3(HID / 32, HID / 32), tb>>>(Wout, wop, HID);

    // 1) QKV projection + bias (tensor cores, fp16 split-2)
    mma_gemm<<<dim3(H3 / 128, S_TOT / 128), 128, GEMM_SMEM>>>(ap, wqp, bqkv, qkv, H3);

    // 2) RoPE + attention-operand split
    int nrope = S_TOT * NH * 36;
    rope_split<<<(nrope + 255) / 256, 256>>>(qkv, cosb, sinb, qp, kp2, vh);

    // 3) Attention (tensor cores) -> writes fp16 [hi|lo] ctx into g_ap
    dim3 ga(8, NH, NSEG);
    attn_mma<<<ga, 256, ATT_SMEM>>>(qp, kp2, vh, ap);

    // 4) Output projection + bias (tensor cores, fp16 split-2)
    mma_gemm<<<dim3(HID / 128, S_TOT / 128), 128, GEMM_SMEM>>>(ap, wop, bout, out, HID);
}

// round 14
// speedup vs baseline: 1.3094x; 1.0119x over previous
#include <cuda_runtime.h>
#include <cuda_bf16.h>
#include <cuda_fp16.h>
#include <cstdint>
#include <cstddef>

// Problem constants
#define S_TOT  8192
#define HID    1152
#define NH     16
#define HD     72
#define NSEG   8
#define LSEG   1024
#define H3     3456
#define ATT_SCALE 0.11785113019775793f   // 72^-0.5
#define LOG2E     1.4426950408889634f
#define QSCALE    (ATT_SCALE * LOG2E)    // softmax in exp2 domain
#define KP2    2304                      // fp16 split-2 K' = 2*1152
#define NST2   (KP2 / 32)                // 72 k-stages of 32
#define QKP    224                       // attention Q'/K' depth (bf16x3): 216 pad 224

// Scratch (allocation-free rule: __device__ globals)
__device__ float g_qkv[(size_t)S_TOT * H3];              // 113 MB
__device__ __half g_ap[(size_t)S_TOT * KP2];             // A' [M][2K] fp16 [hi|lo]
__device__ __half g_wqp[(size_t)H3 * KP2];               // Wqkv'T fp16 [hi|hi]
__device__ __half g_wop[(size_t)HID * KP2];              // Wout'T fp16 [hi|hi]
__device__ __nv_bfloat16 g_qp[(size_t)S_TOT * NH * QKP]; // Q' bf16x3
__device__ __nv_bfloat16 g_kp2[(size_t)S_TOT * NH * QKP];// K' bf16x3
__device__ __half        g_vh[(size_t)S_TOT * NH * 80];  // V fp16; col 72 = 1.0 (l-column)

// ===========================================================================
// PTX helpers (portable sm_80-class only — no tcgen05 on compute_103)
// ===========================================================================
__device__ __forceinline__ uint32_t smem_u32(const void* p) {
    uint32_t a;
    asm("{ .reg .u64 t; cvta.to.shared.u64 t, %1; cvt.u32.u64 %0, t; }"
        : "=r"(a) : "l"(p));
    return a;
}
__device__ __forceinline__ void cp_async16(uint32_t s, const void* g) {
    asm volatile("cp.async.cg.shared.global [%0], [%1], 16;" :: "r"(s), "l"(g));
}
#define CP_COMMIT() asm volatile("cp.async.commit_group;" ::: "memory")
#define CP_WAIT0()  asm volatile("cp.async.wait_group 0;" ::: "memory")
#define CP_WAIT1()  asm volatile("cp.async.wait_group 1;" ::: "memory")

__device__ __forceinline__ void ldm_x4(uint32_t addr, uint32_t& r0, uint32_t& r1,
                                       uint32_t& r2, uint32_t& r3) {
    asm volatile("ldmatrix.sync.aligned.m8n8.x4.shared.b16 {%0,%1,%2,%3}, [%4];"
                 : "=r"(r0), "=r"(r1), "=r"(r2), "=r"(r3) : "r"(addr));
}
__device__ __forceinline__ void ldm_x4_t(uint32_t addr, uint32_t& r0, uint32_t& r1,
                                         uint32_t& r2, uint32_t& r3) {
    asm volatile("ldmatrix.sync.aligned.m8n8.x4.trans.shared.b16 {%0,%1,%2,%3}, [%4];"
                 : "=r"(r0), "=r"(r1), "=r"(r2), "=r"(r3) : "r"(addr));
}
__device__ __forceinline__ void mma16816(float* c, uint32_t a0, uint32_t a1,
                                         uint32_t a2, uint32_t a3,
                                         uint32_t b0, uint32_t b1) {
    asm volatile(
        "mma.sync.aligned.m16n8k16.row.col.f32.bf16.bf16.f32 "
        "{%0,%1,%2,%3}, {%4,%5,%6,%7}, {%8,%9}, {%0,%1,%2,%3};"
        : "+f"(c[0]), "+f"(c[1]), "+f"(c[2]), "+f"(c[3])
        : "r"(a0), "r"(a1), "r"(a2), "r"(a3), "r"(b0), "r"(b1));
}
__device__ __forceinline__ void mma16816h(float* c, uint32_t a0, uint32_t a1,
                                          uint32_t a2, uint32_t a3,
                                          uint32_t b0, uint32_t b1) {
    asm volatile(
        "mma.sync.aligned.m16n8k16.row.col.f32.f16.f16.f32 "
        "{%0,%1,%2,%3}, {%4,%5,%6,%7}, {%8,%9}, {%0,%1,%2,%3};"
        : "+f"(c[0]), "+f"(c[1]), "+f"(c[2]), "+f"(c[3])
        : "r"(a0), "r"(a1), "r"(a2), "r"(a3), "r"(b0), "r"(b1));
}

// ===========================================================================
// Prep: A' = [Ahi | Alo] fp16 along K.  Input [M][1152] fp32.
// ===========================================================================
__global__ void split_A2(const float4* __restrict__ X, __half* __restrict__ ap,
                         int n4)
{
    int i = blockIdx.x * blockDim.x + threadIdx.x;
    if (i >= n4) return;
    int m  = i / (HID / 4);
    int k  = (i % (HID / 4)) * 4;
    float4 x = X[i];
    __half h0 = __float2half(x.x);
    __half h1 = __float2half(x.y);
    __half h2 = __float2half(x.z);
    __half h3 = __float2half(x.w);
    __half l0 = __float2half(x.x - __half2float(h0));
    __half l1 = __float2half(x.y - __half2float(h1));
    __half l2 = __float2half(x.z - __half2float(h2));
    __half l3 = __float2half(x.w - __half2float(h3));
    __half* p = ap + (size_t)m * KP2 + k;
    *(__half2*)(p)           = __half2(h0, h1);
    *(__half2*)(p + 2)       = __half2(h2, h3);
    *(__half2*)(p + HID)     = __half2(l0, l1);
    *(__half2*)(p + HID + 2) = __half2(l2, l3);
}

// Prep: B'T = [Bhi | Bhi] fp16 along K, transposed.
__global__ void split_T2(const float* __restrict__ W, __half* __restrict__ bp,
                         int Nd)
{
    __shared__ float tile[32][33];
    int n0 = blockIdx.x * 32, k0 = blockIdx.y * 32;
    int tx = threadIdx.x, ty = threadIdx.y;   // 32 x 8
    for (int i = ty; i < 32; i += 8)
        tile[i][tx] = W[(size_t)(k0 + i) * Nd + n0 + tx];
    __syncthreads();
    for (int i = ty; i < 32; i += 8) {
        __half h = __float2half(tile[tx][i]);
        __half* row = bp + (size_t)(n0 + i) * KP2;
        row[k0 + tx]       = h;
        row[HID + k0 + tx] = h;
    }
}

// ===========================================================================
// fp16 mma.sync GEMM (R7 structure): C[M,N] = A'[M,KP2] @ B'T[N,KP2] + bias[N]
// 128x128 block, 4 warps (64x64 each), BK=32, 3-stage ring, 2 blocks/SM.
// ===========================================================================
#define STAGE_B 20480                 // A (10240) + B (10240) per stage
#define GEMM_SMEM (3 * STAGE_B)       // 61,440 B

__global__ __launch_bounds__(128, 2) void mma_gemm(
    const __half* __restrict__ Ap, const __half* __restrict__ Bp,
    const float* __restrict__ bias, float* __restrict__ C, int N)
{
    extern __shared__ __align__(16) char sm[];

    const int t    = threadIdx.x;
    const int wid  = t >> 5;
    const int lane = t & 31;
    const int wm   = wid & 1;
    const int wn   = wid >> 1;
    const int m0   = blockIdx.y * 128;
    const int n0   = blockIdx.x * 128;

    const uint32_t sbase = smem_u32(sm);

    float c[4][8][4];
#pragma unroll
    for (int i = 0; i < 4; i++)
#pragma unroll
        for (int j = 0; j < 8; j++)
#pragma unroll
            for (int q = 0; q < 4; q++) c[i][j][q] = 0.f;

    auto load_stage = [&](int st, int k0) {
        uint32_t sA = sbase + st * STAGE_B;
        uint32_t sB = sA + 10240;
#pragma unroll
        for (int rep = 0; rep < 4; rep++) {
            int cidx = t + rep * 128;
            int row = cidx >> 2;
            int seg = cidx & 3;
            uint32_t soff = (uint32_t)(row * 80 + seg * 16);
            cp_async16(sA + soff, Ap + (size_t)(m0 + row) * KP2 + k0 + seg * 8);
            cp_async16(sB + soff, Bp + (size_t)(n0 + row) * KP2 + k0 + seg * 8);
        }
    };

    load_stage(0, 0);  CP_COMMIT();
    load_stage(1, 32); CP_COMMIT();

    const int arow = lane & 15;
    const int acol = (lane >> 4) * 16;
    const int bg   = lane >> 3;
    const int brow = lane & 7;
    const int bnt  = bg >> 1;
    const int bkh  = (bg & 1) * 16;

    int cur = 0;
    for (int kt = 0; kt < NST2; kt++) {
        CP_WAIT1();
        __syncthreads();

        int pf = cur + 2; if (pf >= 3) pf -= 3;
        if (kt + 2 < NST2) load_stage(pf, (kt + 2) * 32);
        CP_COMMIT();

        const uint32_t sA = sbase + cur * STAGE_B;
        const uint32_t sB = sA + 10240;

#pragma unroll
        for (int kk = 0; kk < 2; kk++) {
            const int kb = kk * 32;
            uint32_t a[4][4];
#pragma unroll
            for (int mt = 0; mt < 4; mt++) {
                uint32_t addr = sA
                    + (uint32_t)((wm * 64 + mt * 16 + arow) * 80 + kb + acol);
                ldm_x4(addr, a[mt][0], a[mt][1], a[mt][2], a[mt][3]);
            }
            uint32_t b[8][2];
#pragma unroll
            for (int p = 0; p < 4; p++) {
                uint32_t addr = sB
                    + (uint32_t)((wn * 64 + p * 16 + bnt * 8 + brow) * 80 + kb + bkh);
                uint32_t r0, r1, r2, r3;
                ldm_x4(addr, r0, r1, r2, r3);
                b[p * 2][0] = r0; b[p * 2][1] = r1;
                b[p * 2 + 1][0] = r2; b[p * 2 + 1][1] = r3;
            }
#pragma unroll
            for (int mt = 0; mt < 4; mt++)
#pragma unroll
                for (int nt = 0; nt < 8; nt++)
                    mma16816h(c[mt][nt], a[mt][0], a[mt][1], a[mt][2], a[mt][3],
                              b[nt][0], b[nt][1]);
        }
        cur++; if (cur == 3) cur = 0;
    }

    const int qrow = lane >> 2;
    const int qcol = (lane & 3) * 2;
#pragma unroll
    for (int nt = 0; nt < 8; nt++) {
        int col = n0 + wn * 64 + nt * 8 + qcol;
        float b0 = bias[col], b1 = bias[col + 1];
#pragma unroll
        for (int mt = 0; mt < 4; mt++) {
            int r0 = m0 + wm * 64 + mt * 16 + qrow;
            float2 v0 = make_float2(c[mt][nt][0] + b0, c[mt][nt][1] + b1);
            float2 v1 = make_float2(c[mt][nt][2] + b0, c[mt][nt][3] + b1);
            *(float2*)(C + (size_t)r0 * N + col)       = v0;
            *(float2*)(C + (size_t)(r0 + 8) * N + col) = v1;
        }
    }
}

// ===========================================================================
// RoPE + split for attention operands, 2-wide vectorized (d-pairs).
// Q'/K' bf16x3; V fp16 with the l-column: vh[...][72] = 1.0, 73..79 = 0.
// ===========================================================================
__global__ void rope_split(const float* __restrict__ qkv,
                           const float* __restrict__ cosb,
                           const float* __restrict__ sinb,
                           __nv_bfloat16* __restrict__ qp,
                           __nv_bfloat16* __restrict__ kp,
                           __half* __restrict__ vh)
{
    int idx = blockIdx.x * blockDim.x + threadIdx.x;   // S*NH*18
    if (idx >= S_TOT * NH * 18) return;
    int pr  = idx % 18;          // d-pair index: d = 2*pr (0..34)
    int tmp = idx / 18;
    int h   = tmp % NH;
    int s   = tmp / NH;
    int d   = 2 * pr;

    float2 cs = *(const float2*)(cosb + s * HD + d);
    float2 sn = *(const float2*)(sinb + s * HD + d);
    size_t ib = (size_t)s * H3 + h * HD + d;

    float2 qa = *(const float2*)(qkv + ib);            // dims d, d+1
    float2 qb = *(const float2*)(qkv + ib + 36);       // dims d+36, d+37
    float rq0a = (qa.x * cs.x - qb.x * sn.x) * QSCALE;
    float rq0b = (qa.y * cs.y - qb.y * sn.y) * QSCALE;
    float rq1a = (qb.x * cs.x + qa.x * sn.x) * QSCALE;
    float rq1b = (qb.y * cs.y + qa.y * sn.y) * QSCALE;

    float2 ka = *(const float2*)(qkv + ib + HID);
    float2 kb = *(const float2*)(qkv + ib + HID + 36);
    float rk0a = ka.x * cs.x - kb.x * sn.x;
    float rk0b = ka.y * cs.y - kb.y * sn.y;
    float rk1a = kb.x * cs.x + ka.x * sn.x;
    float rk1b = kb.y * cs.y + ka.y * sn.y;

    float2 va = *(const float2*)(qkv + ib + 2 * HID);
    float2 vb = *(const float2*)(qkv + ib + 2 * HID + 36);

    size_t ob = ((size_t)s * NH + h) * QKP;

    // Q' = [hi | lo | hi]
    {
        __nv_bfloat16 h0a = __float2bfloat16(rq0a), h0b = __float2bfloat16(rq0b);
        __nv_bfloat16 h1a = __float2bfloat16(rq1a), h1b = __float2bfloat16(rq1b);
        __nv_bfloat162 hi0(h0a, h0b), hi1(h1a, h1b);
        __nv_bfloat162 lo0(__float2bfloat16(rq0a - __bfloat162float(h0a)),
                           __float2bfloat16(rq0b - __bfloat162float(h0b)));
        __nv_bfloat162 lo1(__float2bfloat16(rq1a - __bfloat162float(h1a)),
                           __float2bfloat16(rq1b - __bfloat162float(h1b)));
        *(__nv_bfloat162*)(qp + ob + d)            = hi0;
        *(__nv_bfloat162*)(qp + ob + d + 36)       = hi1;
        *(__nv_bfloat162*)(qp + ob + 72 + d)       = lo0;
        *(__nv_bfloat162*)(qp + ob + 72 + d + 36)  = lo1;
        *(__nv_bfloat162*)(qp + ob + 144 + d)      = hi0;
        *(__nv_bfloat162*)(qp + ob + 144 + d + 36) = hi1;
    }
    // K' = [hi | hi | lo]
    {
        __nv_bfloat16 h0a = __float2bfloat16(rk0a), h0b = __float2bfloat16(rk0b);
        __nv_bfloat16 h1a = __float2bfloat16(rk1a), h1b = __float2bfloat16(rk1b);
        __nv_bfloat162 hi0(h0a, h0b), hi1(h1a, h1b);
        __nv_bfloat162 lo0(__float2bfloat16(rk0a - __bfloat162float(h0a)),
                           __float2bfloat16(rk0b - __bfloat162float(h0b)));
        __nv_bfloat162 lo1(__float2bfloat16(rk1a - __bfloat162float(h1a)),
                           __float2bfloat16(rk1b - __bfloat162float(h1b)));
        *(__nv_bfloat162*)(kp + ob + d)            = hi0;
        *(__nv_bfloat162*)(kp + ob + d + 36)       = hi1;
        *(__nv_bfloat162*)(kp + ob + 72 + d)       = hi0;
        *(__nv_bfloat162*)(kp + ob + 72 + d + 36)  = hi1;
        *(__nv_bfloat162*)(kp + ob + 144 + d)      = lo0;
        *(__nv_bfloat162*)(kp + ob + 144 + d + 36) = lo1;
    }

    size_t vbi = ((size_t)s * NH + h) * 80;
    *(__half2*)(vh + vbi + d)      = __floats2half2_rn(va.x, va.y);
    *(__half2*)(vh + vbi + d + 36) = __floats2half2_rn(vb.x, vb.y);

    if (pr < 4) {
        // pads: Q'/K' dims 216..223 = 0; V dims 72..79: col 72 = 1.0 (l-column)
        __nv_bfloat162 z2(__float2bfloat16(0.f), __float2bfloat16(0.f));
        *(__nv_bfloat162*)(qp + ob + 216 + 2 * pr) = z2;
        *(__nv_bfloat162*)(kp + ob + 216 + 2 * pr) = z2;
        *(__half2*)(vh + vbi + 72 + 2 * pr) =
            (pr == 0) ? __floats2half2_rn(1.f, 0.f) : __floats2half2_rn(0.f, 0.f);
    }
}

// ===========================================================================
// FA2-style mma attention (exp2 domain), BQ=128, 3-stage KV ring.
// l computed FREE via the ones-column of V (output col 72).
// Epilogue writes fp16 [hi|lo] ctx directly into g_ap.
// ===========================================================================
#define SQ_BYTES (128 * 464)
#define SK_BYTES (64 * 464)
#define SV_BYTES (64 * 176)
#define KV_STAGE (SK_BYTES + SV_BYTES)        // 40,960
#define ATT_SMEM (SQ_BYTES + 3 * KV_STAGE)    // 182,272

__global__ __launch_bounds__(256, 1) void attn_mma(
    const __nv_bfloat16* __restrict__ Qp, const __nv_bfloat16* __restrict__ Kp,
    const __half* __restrict__ Vh, __half* __restrict__ ap)
{
    extern __shared__ char smA[];
    char* sQ  = smA;
    char* sKV = smA + SQ_BYTES;                // 3 stages of [K | V]

    const int t    = threadIdx.x;
    const int lane = t & 31;
    const int wid  = t >> 5;
    const int qt   = blockIdx.x;     // 0..7
    const int h    = blockIdx.y;     // 0..15
    const int seg  = blockIdx.z;     // 0..7
    const int sbase = seg * LSEG;
    const int qbase = sbase + qt * 128;
    const int q0    = wid * 16;

    auto load_q = [&]() {
        for (int c = t; c < 128 * 28; c += 256) {
            int row = c / 28, ch = c % 28;
            cp_async16(smem_u32(sQ + row * 464 + ch * 16),
                       Qp + ((size_t)(qbase + row) * NH + h) * QKP + ch * 8);
        }
    };
    auto load_kv = [&](int st, int kb) {
        char* dk = sKV + st * KV_STAGE;
        char* dv = dk + SK_BYTES;
        for (int c = t; c < 64 * 28 + 64 * 10; c += 256) {
            if (c < 1792) {
                int row = c / 28, ch = c % 28;
                cp_async16(smem_u32(dk + row * 464 + ch * 16),
                           Kp + ((size_t)(sbase + kb + row) * NH + h) * QKP + ch * 8);
            } else {
                int c2 = c - 1792;
                int row = c2 / 10, ch = c2 % 10;
                cp_async16(smem_u32(dv + row * 176 + ch * 16),
                           Vh + ((size_t)(sbase + kb + row) * NH + h) * 80 + ch * 8);
            }
        }
    };

    load_q(); load_kv(0, 0); CP_COMMIT();
    load_kv(1, 64); CP_COMMIT();

    uint32_t qf[14][4];
    float o[10][4];
#pragma unroll
    for (int j = 0; j < 10; j++)
#pragma unroll
        for (int q = 0; q < 4; q++) o[j][q] = 0.f;
    float m0v = -1e30f, m1v = -1e30f;

    const int qlrow = lane % 16;
    const int qlcol = (lane / 16) * 16;
    const int bkey  = (lane / 16) * 8 + (lane % 8);
    const int bkoff = ((lane / 8) & 1) * 16;
    const int vkey  = ((lane / 8) & 1) * 8 + (lane % 8);
    const int vdoff = (lane / 16) * 16;

    int cur = 0;
    for (int kt = 0; kt < 16; kt++) {
        CP_WAIT1();
        __syncthreads();

        int pf = cur + 2; if (pf >= 3) pf -= 3;
        if (kt + 2 < 16) load_kv(pf, (kt + 2) * 64);
        CP_COMMIT();

        if (kt == 0) {
#pragma unroll
            for (int kk = 0; kk < 14; kk++) {
                uint32_t addr = smem_u32(sQ + (q0 + qlrow) * 464 + kk * 32 + qlcol);
                ldm_x4(addr, qf[kk][0], qf[kk][1], qf[kk][2], qf[kk][3]);
            }
        }

        const char* bk = sKV + cur * KV_STAGE;
        const char* bv = bk + SK_BYTES;

        float s[8][4];
#pragma unroll
        for (int j = 0; j < 8; j++)
#pragma unroll
            for (int q = 0; q < 4; q++) s[j][q] = 0.f;

#pragma unroll
        for (int kk = 0; kk < 14; kk++) {
#pragma unroll
            for (int pr = 0; pr < 4; pr++) {
                uint32_t addr = smem_u32(bk + (pr * 16 + bkey) * 464 + kk * 32 + bkoff);
                uint32_t r0, r1, r2, r3;
                ldm_x4(addr, r0, r1, r2, r3);
                mma16816(s[pr * 2],     qf[kk][0], qf[kk][1], qf[kk][2], qf[kk][3], r0, r1);
                mma16816(s[pr * 2 + 1], qf[kk][0], qf[kk][1], qf[kk][2], qf[kk][3], r2, r3);
            }
        }

        float rx0 = -1e30f, rx1 = -1e30f;
#pragma unroll
        for (int j = 0; j < 8; j++) {
            rx0 = fmaxf(rx0, fmaxf(s[j][0], s[j][1]));
            rx1 = fmaxf(rx1, fmaxf(s[j][2], s[j][3]));
        }
        rx0 = fmaxf(rx0, __shfl_xor_sync(0xffffffffu, rx0, 1));
        rx0 = fmaxf(rx0, __shfl_xor_sync(0xffffffffu, rx0, 2));
        rx1 = fmaxf(rx1, __shfl_xor_sync(0xffffffffu, rx1, 1));
        rx1 = fmaxf(rx1, __shfl_xor_sync(0xffffffffu, rx1, 2));

        float mn0 = fmaxf(m0v, rx0), mn1 = fmaxf(m1v, rx1);
        float a0 = exp2f(m0v - mn0), a1 = exp2f(m1v - mn1);
        m0v = mn0; m1v = mn1;

        // exp2; row-sum comes free from the V ones-column (o[9])
#pragma unroll
        for (int j = 0; j < 8; j++) {
            s[j][0] = exp2f(s[j][0] - mn0);
            s[j][1] = exp2f(s[j][1] - mn0);
            s[j][2] = exp2f(s[j][2] - mn1);
            s[j][3] = exp2f(s[j][3] - mn1);
        }

#pragma unroll
        for (int j = 0; j < 10; j++) {
            o[j][0] *= a0; o[j][1] *= a0;
            o[j][2] *= a1; o[j][3] *= a1;
        }

        uint32_t pa[4][4];
#pragma unroll
        for (int kk2 = 0; kk2 < 4; kk2++) {
            int j = 2 * kk2;
            __half2 h0 = __floats2half2_rn(s[j][0],     s[j][1]);
            __half2 h1 = __floats2half2_rn(s[j][2],     s[j][3]);
            __half2 h2 = __floats2half2_rn(s[j + 1][0], s[j + 1][1]);
            __half2 h3 = __floats2half2_rn(s[j + 1][2], s[j + 1][3]);
            pa[kk2][0] = *(uint32_t*)&h0;
            pa[kk2][1] = *(uint32_t*)&h1;
            pa[kk2][2] = *(uint32_t*)&h2;
            pa[kk2][3] = *(uint32_t*)&h3;
        }

#pragma unroll
        for (int kk2 = 0; kk2 < 4; kk2++) {
#pragma unroll
            for (int vp = 0; vp < 5; vp++) {
                uint32_t addr = smem_u32(bv + (kk2 * 16 + vkey) * 176 + vp * 32 + vdoff);
                uint32_t r0, r1, r2, r3;
                ldm_x4_t(addr, r0, r1, r2, r3);
                mma16816h(o[vp * 2],     pa[kk2][0], pa[kk2][1], pa[kk2][2], pa[kk2][3], r0, r1);
                mma16816h(o[vp * 2 + 1], pa[kk2][0], pa[kk2][1], pa[kk2][2], pa[kk2][3], r2, r3);
            }
        }

        cur++; if (cur == 3) cur = 0;
    }

    // ---- l = ones-column (dim 72 = o[9][0]/o[9][2], held by quad leader) ----
    float l0 = __shfl_sync(0xffffffffu, o[9][0], lane & ~3);
    float l1 = __shfl_sync(0xffffffffu, o[9][2], lane & ~3);
    float inv0 = 1.f / l0, inv1 = 1.f / l1;

    int r_lo = qbase + q0 + lane / 4;
    int r_hi = r_lo + 8;
#pragma unroll
    for (int j = 0; j < 9; j++) {
        int col = h * HD + j * 8 + (lane & 3) * 2;
        float x0 = o[j][0] * inv0, x1 = o[j][1] * inv0;
        float x2 = o[j][2] * inv1, x3 = o[j][3] * inv1;

        __half hx0 = __float2half(x0);
        __half hx1 = __float2half(x1);
        __half lx0 = __float2half(x0 - __half2float(hx0));
        __half lx1 = __float2half(x1 - __half2float(hx1));
        __half* row0 = ap + (size_t)r_lo * KP2 + col;
        *(__half2*)(row0)       = __half2(hx0, hx1);
        *(__half2*)(row0 + HID) = __half2(lx0, lx1);

        __half hx2 = __float2half(x2);
        __half hx3 = __float2half(x3);
        __half lx2 = __float2half(x2 - __half2float(hx2));
        __half lx3 = __float2half(x3 - __half2float(hx3));
        __half* row1 = ap + (size_t)r_hi * KP2 + col;
        *(__half2*)(row1)       = __half2(hx2, hx3);
        *(__half2*)(row1 + HID) = __half2(lx2, lx3);
    }
}

// ===========================================================================
// Launch
// ===========================================================================
extern "C" void kernel_launch(void* const* d_in, const int* in_sizes, int n_in,
                              void* d_out, int out_size)
{
    const float* hidden = (const float*)d_in[0];
    const float* cosb   = (const float*)d_in[1];
    const float* sinb   = (const float*)d_in[2];
    const float* Wqkv   = (const float*)d_in[3];
    const float* bqkv   = (const float*)d_in[4];
    const float* Wout   = (const float*)d_in[5];
    const float* bout   = (const float*)d_in[6];
    float* out = (float*)d_out;

    float *qkv;
    __half *ap, *wqp, *wop, *vh;
    __nv_bfloat16 *qp, *kp2;
    cudaGetSymbolAddress((void**)&qkv, g_qkv);
    cudaGetSymbolAddress((void**)&ap, g_ap);
    cudaGetSymbolAddress((void**)&wqp, g_wqp);
    cudaGetSymbolAddress((void**)&wop, g_wop);
    cudaGetSymbolAddress((void**)&qp, g_qp);
    cudaGetSymbolAddress((void**)&kp2, g_kp2);
    cudaGetSymbolAddress((void**)&vh, g_vh);

    cudaFuncSetAttribute(mma_gemm, cudaFuncAttributeMaxDynamicSharedMemorySize, GEMM_SMEM);
    cudaFuncSetAttribute(attn_mma, cudaFuncAttributeMaxDynamicSharedMemorySize, ATT_SMEM);

    int n4 = S_TOT * HID / 4;

    // Prep: fp16 split-2 operands
    split_A2<<<(n4 + 255) / 256, 256>>>((const float4*)hidden, ap, n4);
    dim3 tb(32, 8);
    split_T2<<<dim3(H3 / 32, HID / 32), tb>>>(Wqkv, wqp, H3);
    split_T2<<<dim3(HID / 32, HID / 32), tb>>>(Wout, wop, HID);

    // 1) QKV projection + bias (tensor cores, fp16 split-2)
    mma_gemm<<<dim3(H3 / 128, S_TOT / 128), 128, GEMM_SMEM>>>(ap, wqp, bqkv, qkv, H3);

    // 2) RoPE + attention-operand split (2-wide vectorized)
    int nrope = S_TOT * NH * 18;
    rope_split<<<(nrope + 255) / 256, 256>>>(qkv, cosb, sinb, qp, kp2, vh);

    // 3) Attention (tensor cores) -> writes fp16 [hi|lo] ctx into g_ap
    dim3 ga(8, NH, NSEG);
    attn_mma<<<ga, 256, ATT_SMEM>>>(qp, kp2, vh, ap);

    // 4) Output projection + bias (tensor cores, fp16 split-2)
    mma_gemm<<<dim3(HID / 128, S_TOT / 128), 128, GEMM_SMEM>>>(ap, wop, bout, out, HID);
}

// round 15
// speedup vs baseline: 1.3866x; 1.0590x over previous
#include <cuda_runtime.h>
#include <cuda_bf16.h>
#include <cuda_fp16.h>
#include <cstdint>
#include <cstddef>

// Problem constants
#define S_TOT  8192
#define HID    1152
#define NH     16
#define HD     72
#define NSEG   8
#define LSEG   1024
#define H3     3456
#define ATT_SCALE 0.11785113019775793f   // 72^-0.5
#define LOG2E     1.4426950408889634f
#define QSCALE    (ATT_SCALE * LOG2E)    // softmax in exp2 domain
#define KP2    2304                      // fp16 split-2 K' = 2*1152
#define NSTG   (KP2 / 64)                // 36 k-stages of 64
#define QKP    224                       // attention Q'/K' depth (bf16x3): 216 pad 224

// Scratch (allocation-free rule: __device__ globals)
__device__ float g_qkv[(size_t)S_TOT * H3];              // 113 MB
__device__ __half g_ap[(size_t)S_TOT * KP2];             // A' [M][2K] fp16 [hi|lo]
__device__ __half g_wqp[(size_t)H3 * KP2];               // Wqkv'T fp16 [hi|hi]
__device__ __half g_wop[(size_t)HID * KP2];              // Wout'T fp16 [hi|hi]
__device__ __nv_bfloat16 g_qp[(size_t)S_TOT * NH * QKP]; // Q' bf16x3
__device__ __nv_bfloat16 g_kp2[(size_t)S_TOT * NH * QKP];// K' bf16x3
__device__ __half        g_vh[(size_t)S_TOT * NH * 80];  // V fp16; col 72 = 1.0 (l-column)

// ===========================================================================
// PTX helpers (portable sm_80-class only — no tcgen05 on compute_103)
// ===========================================================================
__device__ __forceinline__ uint32_t smem_u32(const void* p) {
    uint32_t a;
    asm("{ .reg .u64 t; cvta.to.shared.u64 t, %1; cvt.u32.u64 %0, t; }"
        : "=r"(a) : "l"(p));
    return a;
}
__device__ __forceinline__ void cp_async16(uint32_t s, const void* g) {
    asm volatile("cp.async.cg.shared.global [%0], [%1], 16;" :: "r"(s), "l"(g));
}
#define CP_COMMIT() asm volatile("cp.async.commit_group;" ::: "memory")
#define CP_WAIT0()  asm volatile("cp.async.wait_group 0;" ::: "memory")
#define CP_WAIT1()  asm volatile("cp.async.wait_group 1;" ::: "memory")

__device__ __forceinline__ void ldm_x4(uint32_t addr, uint32_t& r0, uint32_t& r1,
                                       uint32_t& r2, uint32_t& r3) {
    asm volatile("ldmatrix.sync.aligned.m8n8.x4.shared.b16 {%0,%1,%2,%3}, [%4];"
                 : "=r"(r0), "=r"(r1), "=r"(r2), "=r"(r3) : "r"(addr));
}
__device__ __forceinline__ void ldm_x4_t(uint32_t addr, uint32_t& r0, uint32_t& r1,
                                         uint32_t& r2, uint32_t& r3) {
    asm volatile("ldmatrix.sync.aligned.m8n8.x4.trans.shared.b16 {%0,%1,%2,%3}, [%4];"
                 : "=r"(r0), "=r"(r1), "=r"(r2), "=r"(r3) : "r"(addr));
}
__device__ __forceinline__ void mma16816(float* c, uint32_t a0, uint32_t a1,
                                         uint32_t a2, uint32_t a3,
                                         uint32_t b0, uint32_t b1) {
    asm volatile(
        "mma.sync.aligned.m16n8k16.row.col.f32.bf16.bf16.f32 "
        "{%0,%1,%2,%3}, {%4,%5,%6,%7}, {%8,%9}, {%0,%1,%2,%3};"
        : "+f"(c[0]), "+f"(c[1]), "+f"(c[2]), "+f"(c[3])
        : "r"(a0), "r"(a1), "r"(a2), "r"(a3), "r"(b0), "r"(b1));
}
__device__ __forceinline__ void mma16816h(float* c, uint32_t a0, uint32_t a1,
                                          uint32_t a2, uint32_t a3,
                                          uint32_t b0, uint32_t b1) {
    asm volatile(
        "mma.sync.aligned.m16n8k16.row.col.f32.f16.f16.f32 "
        "{%0,%1,%2,%3}, {%4,%5,%6,%7}, {%8,%9}, {%0,%1,%2,%3};"
        : "+f"(c[0]), "+f"(c[1]), "+f"(c[2]), "+f"(c[3])
        : "r"(a0), "r"(a1), "r"(a2), "r"(a3), "r"(b0), "r"(b1));
}

// ===========================================================================
// Prep: A' = [Ahi | Alo] fp16 along K.  Input [M][1152] fp32.
// ===========================================================================
__global__ void split_A2(const float4* __restrict__ X, __half* __restrict__ ap,
                         int n4)
{
    int i = blockIdx.x * blockDim.x + threadIdx.x;
    if (i >= n4) return;
    int m  = i / (HID / 4);
    int k  = (i % (HID / 4)) * 4;
    float4 x = X[i];
    __half h0 = __float2half(x.x);
    __half h1 = __float2half(x.y);
    __half h2 = __float2half(x.z);
    __half h3 = __float2half(x.w);
    __half l0 = __float2half(x.x - __half2float(h0));
    __half l1 = __float2half(x.y - __half2float(h1));
    __half l2 = __float2half(x.z - __half2float(h2));
    __half l3 = __float2half(x.w - __half2float(h3));
    __half* p = ap + (size_t)m * KP2 + k;
    *(__half2*)(p)           = __half2(h0, h1);
    *(__half2*)(p + 2)       = __half2(h2, h3);
    *(__half2*)(p + HID)     = __half2(l0, l1);
    *(__half2*)(p + HID + 2) = __half2(l2, l3);
}

// Prep: B'T = [Bhi | Bhi] fp16 along K, transposed.
__global__ void split_T2(const float* __restrict__ W, __half* __restrict__ bp,
                         int Nd)
{
    __shared__ float tile[32][33];
    int n0 = blockIdx.x * 32, k0 = blockIdx.y * 32;
    int tx = threadIdx.x, ty = threadIdx.y;   // 32 x 8
    for (int i = ty; i < 32; i += 8)
        tile[i][tx] = W[(size_t)(k0 + i) * Nd + n0 + tx];
    __syncthreads();
    for (int i = ty; i < 32; i += 8) {
        __half h = __float2half(tile[tx][i]);
        __half* row = bp + (size_t)(n0 + i) * KP2;
        row[k0 + tx]       = h;
        row[HID + k0 + tx] = h;
    }
}

// ===========================================================================
// fp16 mma.sync GEMM: 128x128 block, 4 warps (64x64 each), BK=64,
// XOR-swizzled 128B rows, 3-stage ring (one sync/stage), 2 blocks/SM.
// ===========================================================================
#define ROWB 128                       // bytes per smem row (64 fp16), swizzled
#define OP_B (128 * ROWB)              // 16,384 per operand
#define STAGE_B (2 * OP_B)             // 32,768 per stage
#define GEMM_SMEM (3 * STAGE_B)        // 98,304 B

__global__ __launch_bounds__(128, 2) void mma_gemm(
    const __half* __restrict__ Ap, const __half* __restrict__ Bp,
    const float* __restrict__ bias, float* __restrict__ C, int N)
{
    extern __shared__ __align__(16) char sm[];

    const int t    = threadIdx.x;
    const int wid  = t >> 5;
    const int lane = t & 31;
    const int wm   = wid & 1;
    const int wn   = wid >> 1;
    const int m0   = blockIdx.y * 128;
    const int n0   = blockIdx.x * 128;

    const uint32_t sbase = smem_u32(sm);

    float c[4][8][4];
#pragma unroll
    for (int i = 0; i < 4; i++)
#pragma unroll
        for (int j = 0; j < 8; j++)
#pragma unroll
            for (int q = 0; q < 4; q++) c[i][j][q] = 0.f;

    // stage: A rows (swizzled chunks), then B at +OP_B
    auto load_stage = [&](int st, int k0) {
        uint32_t sA = sbase + st * STAGE_B;
        uint32_t sB = sA + OP_B;
#pragma unroll
        for (int rep = 0; rep < 8; rep++) {
            int cidx = t + rep * 128;          // 0..1023
            int row = cidx >> 3;
            int seg = cidx & 7;
            uint32_t soff = (uint32_t)(row * ROWB + ((seg ^ (row & 7)) << 4));
            cp_async16(sA + soff, Ap + (size_t)(m0 + row) * KP2 + k0 + seg * 8);
            cp_async16(sB + soff, Bp + (size_t)(n0 + row) * KP2 + k0 + seg * 8);
        }
    };

    load_stage(0, 0);   CP_COMMIT();
    load_stage(1, 64);  CP_COMMIT();

    const int arow = lane & 15;
    const int ach  = lane >> 4;          // logical chunk half (0/1)
    const int bg   = lane >> 3;
    const int brow = lane & 7;
    const int bnt  = bg >> 1;
    const int bch  = bg & 1;

    int cur = 0;
    for (int kt = 0; kt < NSTG; kt++) {
        CP_WAIT1();
        __syncthreads();

        int pf = cur + 2; if (pf >= 3) pf -= 3;
        if (kt + 2 < NSTG) load_stage(pf, (kt + 2) * 64);
        CP_COMMIT();

        const uint32_t sA = sbase + cur * STAGE_B;
        const uint32_t sB = sA + OP_B;

#pragma unroll
        for (int kk = 0; kk < 4; kk++) {
            uint32_t a[4][4];
#pragma unroll
            for (int mt = 0; mt < 4; mt++) {
                int row = wm * 64 + mt * 16 + arow;
                int lch = 2 * kk + ach;
                uint32_t addr = sA + (uint32_t)(row * ROWB + ((lch ^ (row & 7)) << 4));
                ldm_x4(addr, a[mt][0], a[mt][1], a[mt][2], a[mt][3]);
            }
            uint32_t b[8][2];
#pragma unroll
            for (int p = 0; p < 4; p++) {
                int row = wn * 64 + p * 16 + bnt * 8 + brow;
                int lch = 2 * kk + bch;
                uint32_t addr = sB + (uint32_t)(row * ROWB + ((lch ^ (row & 7)) << 4));
                uint32_t r0, r1, r2, r3;
                ldm_x4(addr, r0, r1, r2, r3);
                b[p * 2][0] = r0; b[p * 2][1] = r1;
                b[p * 2 + 1][0] = r2; b[p * 2 + 1][1] = r3;
            }
#pragma unroll
            for (int mt = 0; mt < 4; mt++)
#pragma unroll
                for (int nt = 0; nt < 8; nt++)
                    mma16816h(c[mt][nt], a[mt][0], a[mt][1], a[mt][2], a[mt][3],
                              b[nt][0], b[nt][1]);
        }
        cur++; if (cur == 3) cur = 0;
    }

    const int qrow = lane >> 2;
    const int qcol = (lane & 3) * 2;
#pragma unroll
    for (int nt = 0; nt < 8; nt++) {
        int col = n0 + wn * 64 + nt * 8 + qcol;
        float b0 = bias[col], b1 = bias[col + 1];
#pragma unroll
        for (int mt = 0; mt < 4; mt++) {
            int r0 = m0 + wm * 64 + mt * 16 + qrow;
            float2 v0 = make_float2(c[mt][nt][0] + b0, c[mt][nt][1] + b1);
            float2 v1 = make_float2(c[mt][nt][2] + b0, c[mt][nt][3] + b1);
            *(float2*)(C + (size_t)r0 * N + col)       = v0;
            *(float2*)(C + (size_t)(r0 + 8) * N + col) = v1;
        }
    }
}

// ===========================================================================
// RoPE + split for attention operands, 2-wide vectorized (d-pairs).
// Q'/K' bf16x3; V fp16 with the l-column: vh[...][72] = 1.0, 73..79 = 0.
// ===========================================================================
__global__ void rope_split(const float* __restrict__ qkv,
                           const float* __restrict__ cosb,
                           const float* __restrict__ sinb,
                           __nv_bfloat16* __restrict__ qp,
                           __nv_bfloat16* __restrict__ kp,
                           __half* __restrict__ vh)
{
    int idx = blockIdx.x * blockDim.x + threadIdx.x;   // S*NH*18
    if (idx >= S_TOT * NH * 18) return;
    int pr  = idx % 18;
    int tmp = idx / 18;
    int h   = tmp % NH;
    int s   = tmp / NH;
    int d   = 2 * pr;

    float2 cs = *(const float2*)(cosb + s * HD + d);
    float2 sn = *(const float2*)(sinb + s * HD + d);
    size_t ib = (size_t)s * H3 + h * HD + d;

    float2 qa = *(const float2*)(qkv + ib);
    float2 qb = *(const float2*)(qkv + ib + 36);
    float rq0a = (qa.x * cs.x - qb.x * sn.x) * QSCALE;
    float rq0b = (qa.y * cs.y - qb.y * sn.y) * QSCALE;
    float rq1a = (qb.x * cs.x + qa.x * sn.x) * QSCALE;
    float rq1b = (qb.y * cs.y + qa.y * sn.y) * QSCALE;

    float2 ka = *(const float2*)(qkv + ib + HID);
    float2 kb = *(const float2*)(qkv + ib + HID + 36);
    float rk0a = ka.x * cs.x - kb.x * sn.x;
    float rk0b = ka.y * cs.y - kb.y * sn.y;
    float rk1a = kb.x * cs.x + ka.x * sn.x;
    float rk1b = kb.y * cs.y + ka.y * sn.y;

    float2 va = *(const float2*)(qkv + ib + 2 * HID);
    float2 vb = *(const float2*)(qkv + ib + 2 * HID + 36);

    size_t ob = ((size_t)s * NH + h) * QKP;

    {
        __nv_bfloat16 h0a = __float2bfloat16(rq0a), h0b = __float2bfloat16(rq0b);
        __nv_bfloat16 h1a = __float2bfloat16(rq1a), h1b = __float2bfloat16(rq1b);
        __nv_bfloat162 hi0(h0a, h0b), hi1(h1a, h1b);
        __nv_bfloat162 lo0(__float2bfloat16(rq0a - __bfloat162float(h0a)),
                           __float2bfloat16(rq0b - __bfloat162float(h0b)));
        __nv_bfloat162 lo1(__float2bfloat16(rq1a - __bfloat162float(h1a)),
                           __float2bfloat16(rq1b - __bfloat162float(h1b)));
        *(__nv_bfloat162*)(qp + ob + d)            = hi0;
        *(__nv_bfloat162*)(qp + ob + d + 36)       = hi1;
        *(__nv_bfloat162*)(qp + ob + 72 + d)       = lo0;
        *(__nv_bfloat162*)(qp + ob + 72 + d + 36)  = lo1;
        *(__nv_bfloat162*)(qp + ob + 144 + d)      = hi0;
        *(__nv_bfloat162*)(qp + ob + 144 + d + 36) = hi1;
    }
    {
        __nv_bfloat16 h0a = __float2bfloat16(rk0a), h0b = __float2bfloat16(rk0b);
        __nv_bfloat16 h1a = __float2bfloat16(rk1a), h1b = __float2bfloat16(rk1b);
        __nv_bfloat162 hi0(h0a, h0b), hi1(h1a, h1b);
        __nv_bfloat162 lo0(__float2bfloat16(rk0a - __bfloat162float(h0a)),
                           __float2bfloat16(rk0b - __bfloat162float(h0b)));
        __nv_bfloat162 lo1(__float2bfloat16(rk1a - __bfloat162float(h1a)),
                           __float2bfloat16(rk1b - __bfloat162float(h1b)));
        *(__nv_bfloat162*)(kp + ob + d)            = hi0;
        *(__nv_bfloat162*)(kp + ob + d + 36)       = hi1;
        *(__nv_bfloat162*)(kp + ob + 72 + d)       = hi0;
        *(__nv_bfloat162*)(kp + ob + 72 + d + 36)  = hi1;
        *(__nv_bfloat162*)(kp + ob + 144 + d)      = lo0;
        *(__nv_bfloat162*)(kp + ob + 144 + d + 36) = lo1;
    }

    size_t vbi = ((size_t)s * NH + h) * 80;
    *(__half2*)(vh + vbi + d)      = __floats2half2_rn(va.x, va.y);
    *(__half2*)(vh + vbi + d + 36) = __floats2half2_rn(vb.x, vb.y);

    if (pr < 4) {
        __nv_bfloat162 z2(__float2bfloat16(0.f), __float2bfloat16(0.f));
        *(__nv_bfloat162*)(qp + ob + 216 + 2 * pr) = z2;
        *(__nv_bfloat162*)(kp + ob + 216 + 2 * pr) = z2;
        *(__half2*)(vh + vbi + 72 + 2 * pr) =
            (pr == 0) ? __floats2half2_rn(1.f, 0.f) : __floats2half2_rn(0.f, 0.f);
    }
}

// ===========================================================================
// FA2-style mma attention (exp2 domain), BQ=128, 3-stage KV ring.
// l computed FREE via the ones-column of V (output col 72).
// Epilogue writes fp16 [hi|lo] ctx directly into g_ap.
// ===========================================================================
#define SQ_BYTES (128 * 464)
#define SK_BYTES (64 * 464)
#define SV_BYTES (64 * 176)
#define KV_STAGE (SK_BYTES + SV_BYTES)        // 40,960
#define ATT_SMEM (SQ_BYTES + 3 * KV_STAGE)    // 182,272

__global__ __launch_bounds__(256, 1) void attn_mma(
    const __nv_bfloat16* __restrict__ Qp, const __nv_bfloat16* __restrict__ Kp,
    const __half* __restrict__ Vh, __half* __restrict__ ap)
{
    extern __shared__ char smA[];
    char* sQ  = smA;
    char* sKV = smA + SQ_BYTES;

    const int t    = threadIdx.x;
    const int lane = t & 31;
    const int wid  = t >> 5;
    const int qt   = blockIdx.x;
    const int h    = blockIdx.y;
    const int seg  = blockIdx.z;
    const int sbase = seg * LSEG;
    const int qbase = sbase + qt * 128;
    const int q0    = wid * 16;

    auto load_q = [&]() {
        for (int c = t; c < 128 * 28; c += 256) {
            int row = c / 28, ch = c % 28;
            cp_async16(smem_u32(sQ + row * 464 + ch * 16),
                       Qp + ((size_t)(qbase + row) * NH + h) * QKP + ch * 8);
        }
    };
    auto load_kv = [&](int st, int kb) {
        char* dk = sKV + st * KV_STAGE;
        char* dv = dk + SK_BYTES;
        for (int c = t; c < 64 * 28 + 64 * 10; c += 256) {
            if (c < 1792) {
                int row = c / 28, ch = c % 28;
                cp_async16(smem_u32(dk + row * 464 + ch * 16),
                           Kp + ((size_t)(sbase + kb + row) * NH + h) * QKP + ch * 8);
            } else {
                int c2 = c - 1792;
                int row = c2 / 10, ch = c2 % 10;
                cp_async16(smem_u32(dv + row * 176 + ch * 16),
                           Vh + ((size_t)(sbase + kb + row) * NH + h) * 80 + ch * 8);
            }
        }
    };

    load_q(); load_kv(0, 0); CP_COMMIT();
    load_kv(1, 64); CP_COMMIT();

    uint32_t qf[14][4];
    float o[10][4];
#pragma unroll
    for (int j = 0; j < 10; j++)
#pragma unroll
        for (int q = 0; q < 4; q++) o[j][q] = 0.f;
    float m0v = -1e30f, m1v = -1e30f;

    const int qlrow = lane % 16;
    const int qlcol = (lane / 16) * 16;
    const int bkey  = (lane / 16) * 8 + (lane % 8);
    const int bkoff = ((lane / 8) & 1) * 16;
    const int vkey  = ((lane / 8) & 1) * 8 + (lane % 8);
    const int vdoff = (lane / 16) * 16;

    int cur = 0;
    for (int kt = 0; kt < 16; kt++) {
        CP_WAIT1();
        __syncthreads();

        int pf = cur + 2; if (pf >= 3) pf -= 3;
        if (kt + 2 < 16) load_kv(pf, (kt + 2) * 64);
        CP_COMMIT();

        if (kt == 0) {
#pragma unroll
            for (int kk = 0; kk < 14; kk++) {
                uint32_t addr = smem_u32(sQ + (q0 + qlrow) * 464 + kk * 32 + qlcol);
                ldm_x4(addr, qf[kk][0], qf[kk][1], qf[kk][2], qf[kk][3]);
            }
        }

        const char* bk = sKV + cur * KV_STAGE;
        const char* bv = bk + SK_BYTES;

        float s[8][4];
#pragma unroll
        for (int j = 0; j < 8; j++)
#pragma unroll
            for (int q = 0; q < 4; q++) s[j][q] = 0.f;

#pragma unroll
        for (int kk = 0; kk < 14; kk++) {
#pragma unroll
            for (int pr = 0; pr < 4; pr++) {
                uint32_t addr = smem_u32(bk + (pr * 16 + bkey) * 464 + kk * 32 + bkoff);
                uint32_t r0, r1, r2, r3;
                ldm_x4(addr, r0, r1, r2, r3);
                mma16816(s[pr * 2],     qf[kk][0], qf[kk][1], qf[kk][2], qf[kk][3], r0, r1);
                mma16816(s[pr * 2 + 1], qf[kk][0], qf[kk][1], qf[kk][2], qf[kk][3], r2, r3);
            }
        }

        float rx0 = -1e30f, rx1 = -1e30f;
#pragma unroll
        for (int j = 0; j < 8; j++) {
            rx0 = fmaxf(rx0, fmaxf(s[j][0], s[j][1]));
            rx1 = fmaxf(rx1, fmaxf(s[j][2], s[j][3]));
        }
        rx0 = fmaxf(rx0, __shfl_xor_sync(0xffffffffu, rx0, 1));
        rx0 = fmaxf(rx0, __shfl_xor_sync(0xffffffffu, rx0, 2));
        rx1 = fmaxf(rx1, __shfl_xor_sync(0xffffffffu, rx1, 1));
        rx1 = fmaxf(rx1, __shfl_xor_sync(0xffffffffu, rx1, 2));

        float mn0 = fmaxf(m0v, rx0), mn1 = fmaxf(m1v, rx1);
        float a0 = exp2f(m0v - mn0), a1 = exp2f(m1v - mn1);
        m0v = mn0; m1v = mn1;

#pragma unroll
        for (int j = 0; j < 8; j++) {
            s[j][0] = exp2f(s[j][0] - mn0);
            s[j][1] = exp2f(s[j][1] - mn0);
            s[j][2] = exp2f(s[j][2] - mn1);
            s[j][3] = exp2f(s[j][3] - mn1);
        }

#pragma unroll
        for (int j = 0; j < 10; j++) {
            o[j][0] *= a0; o[j][1] *= a0;
            o[j][2] *= a1; o[j][3] *= a1;
        }

        uint32_t pa[4][4];
#pragma unroll
        for (int kk2 = 0; kk2 < 4; kk2++) {
            int j = 2 * kk2;
            __half2 h0 = __floats2half2_rn(s[j][0],     s[j][1]);
            __half2 h1 = __floats2half2_rn(s[j][2],     s[j][3]);
            __half2 h2 = __floats2half2_rn(s[j + 1][0], s[j + 1][1]);
            __half2 h3 = __floats2half2_rn(s[j + 1][2], s[j + 1][3]);
            pa[kk2][0] = *(uint32_t*)&h0;
            pa[kk2][1] = *(uint32_t*)&h1;
            pa[kk2][2] = *(uint32_t*)&h2;
            pa[kk2][3] = *(uint32_t*)&h3;
        }

#pragma unroll
        for (int kk2 = 0; kk2 < 4; kk2++) {
#pragma unroll
            for (int vp = 0; vp < 5; vp++) {
                uint32_t addr = smem_u32(bv + (kk2 * 16 + vkey) * 176 + vp * 32 + vdoff);
                uint32_t r0, r1, r2, r3;
                ldm_x4_t(addr, r0, r1, r2, r3);
                mma16816h(o[vp * 2],     pa[kk2][0], pa[kk2][1], pa[kk2][2], pa[kk2][3], r0, r1);
                mma16816h(o[vp * 2 + 1], pa[kk2][0], pa[kk2][1], pa[kk2][2], pa[kk2][3], r2, r3);
            }
        }

        cur++; if (cur == 3) cur = 0;
    }

    float l0 = __shfl_sync(0xffffffffu, o[9][0], lane & ~3);
    float l1 = __shfl_sync(0xffffffffu, o[9][2], lane & ~3);
    float inv0 = 1.f / l0, inv1 = 1.f / l1;

    int r_lo = qbase + q0 + lane / 4;
    int r_hi = r_lo + 8;
#pragma unroll
    for (int j = 0; j < 9; j++) {
        int col = h * HD + j * 8 + (lane & 3) * 2;
        float x0 = o[j][0] * inv0, x1 = o[j][1] * inv0;
        float x2 = o[j][2] * inv1, x3 = o[j][3] * inv1;

        __half hx0 = __float2half(x0);
        __half hx1 = __float2half(x1);
        __half lx0 = __float2half(x0 - __half2float(hx0));
        __half lx1 = __float2half(x1 - __half2float(hx1));
        __half* row0 = ap + (size_t)r_lo * KP2 + col;
        *(__half2*)(row0)       = __half2(hx0, hx1);
        *(__half2*)(row0 + HID) = __half2(lx0, lx1);

        __half hx2 = __float2half(x2);
        __half hx3 = __float2half(x3);
        __half lx2 = __float2half(x2 - __half2float(hx2));
        __half lx3 = __float2half(x3 - __half2float(hx3));
        __half* row1 = ap + (size_t)r_hi * KP2 + col;
        *(__half2*)(row1)       = __half2(hx2, hx3);
        *(__half2*)(row1 + HID) = __half2(lx2, lx3);
    }
}

// ===========================================================================
// Launch
// ===========================================================================
extern "C" void kernel_launch(void* const* d_in, const int* in_sizes, int n_in,
                              void* d_out, int out_size)
{
    const float* hidden = (const float*)d_in[0];
    const float* cosb   = (const float*)d_in[1];
    const float* sinb   = (const float*)d_in[2];
    const float* Wqkv   = (const float*)d_in[3];
    const float* bqkv   = (const float*)d_in[4];
    const float* Wout   = (const float*)d_in[5];
    const float* bout   = (const float*)d_in[6];
    float* out = (float*)d_out;

    float *qkv;
    __half *ap, *wqp, *wop, *vh;
    __nv_bfloat16 *qp, *kp2;
    cudaGetSymbolAddress((void**)&qkv, g_qkv);
    cudaGetSymbolAddress((void**)&ap, g_ap);
    cudaGetSymbolAddress((void**)&wqp, g_wqp);
    cudaGetSymbolAddress((void**)&wop, g_wop);
    cudaGetSymbolAddress((void**)&qp, g_qp);
    cudaGetSymbolAddress((void**)&kp2, g_kp2);
    cudaGetSymbolAddress((void**)&vh, g_vh);

    cudaFuncSetAttribute(mma_gemm, cudaFuncAttributeMaxDynamicSharedMemorySize, GEMM_SMEM);
    cudaFuncSetAttribute(attn_mma, cudaFuncAttributeMaxDynamicSharedMemorySize, ATT_SMEM);

    int n4 = S_TOT * HID / 4;

    // Prep: fp16 split-2 operands
    split_A2<<<(n4 + 255) / 256, 256>>>((const float4*)hidden, ap, n4);
    dim3 tb(32, 8);
    split_T2<<<dim3(H3 / 32, HID / 32), tb>>>(Wqkv, wqp, H3);
    split_T2<<<dim3(HID / 32, HID / 32), tb>>>(Wout, wop, HID);

    // 1) QKV projection + bias (tensor cores, fp16 split-2, BK=64)
    mma_gemm<<<dim3(H3 / 128, S_TOT / 128), 128, GEMM_SMEM>>>(ap, wqp, bqkv, qkv, H3);

    // 2) RoPE + attention-operand split (2-wide vectorized)
    int nrope = S_TOT * NH * 18;
    rope_split<<<(nrope + 255) / 256, 256>>>(qkv, cosb, sinb, qp, kp2, vh);

    // 3) Attention (tensor cores) -> writes fp16 [hi|lo] ctx into g_ap
    dim3 ga(8, NH, NSEG);
    attn_mma<<<ga, 256, ATT_SMEM>>>(qp, kp2, vh, ap);

    // 4) Output projection + bias (tensor cores, fp16 split-2, BK=64)
    mma_gemm<<<dim3(HID / 128, S_TOT / 128), 128, GEMM_SMEM>>>(ap, wop, bout, out, HID);
}

// round 16
// speedup vs baseline: 1.5088x; 1.0882x over previous
#include <cuda_runtime.h>
#include <cuda_bf16.h>
#include <cuda_fp16.h>
#include <cstdint>
#include <cstddef>

// Problem constants
#define S_TOT  8192
#define HID    1152
#define NH     16
#define HD     72
#define NSEG   8
#define LSEG   1024
#define H3     3456
#define ATT_SCALE 0.11785113019775793f   // 72^-0.5
#define LOG2E     1.4426950408889634f
#define QSCALE    (ATT_SCALE * LOG2E)    // softmax in exp2 domain
#define KP2    2304                      // fp16 split-2 K' = 2*1152 (GEMMs)
#define NSTG   (KP2 / 64)                // 36 k-stages of 64
#define QKP    160                       // attention Q'/K' depth (fp16 split-2): 144 pad 160

// Scratch (allocation-free rule: __device__ globals)
__device__ float g_qkv[(size_t)S_TOT * H3];              // 113 MB
__device__ __half g_ap[(size_t)S_TOT * KP2];             // A' [M][2K] fp16 [hi|lo]
__device__ __half g_wqp[(size_t)H3 * KP2];               // Wqkv'T fp16 [hi|hi]
__device__ __half g_wop[(size_t)HID * KP2];              // Wout'T fp16 [hi|hi]
__device__ __half g_qp[(size_t)S_TOT * NH * QKP];        // Q' fp16 [hi|lo] [s][h][160]
__device__ __half g_kp2[(size_t)S_TOT * NH * QKP];       // K' fp16 [hi|hi]
__device__ __half g_vh[(size_t)S_TOT * NH * 80];         // V fp16; col 72 = 1.0 (l-column)

// ===========================================================================
// PTX helpers (portable sm_80-class only — no tcgen05 on compute_103)
// ===========================================================================
__device__ __forceinline__ uint32_t smem_u32(const void* p) {
    uint32_t a;
    asm("{ .reg .u64 t; cvta.to.shared.u64 t, %1; cvt.u32.u64 %0, t; }"
        : "=r"(a) : "l"(p));
    return a;
}
__device__ __forceinline__ void cp_async16(uint32_t s, const void* g) {
    asm volatile("cp.async.cg.shared.global [%0], [%1], 16;" :: "r"(s), "l"(g));
}
#define CP_COMMIT() asm volatile("cp.async.commit_group;" ::: "memory")
#define CP_WAIT0()  asm volatile("cp.async.wait_group 0;" ::: "memory")
#define CP_WAIT1()  asm volatile("cp.async.wait_group 1;" ::: "memory")

__device__ __forceinline__ void ldm_x4(uint32_t addr, uint32_t& r0, uint32_t& r1,
                                       uint32_t& r2, uint32_t& r3) {
    asm volatile("ldmatrix.sync.aligned.m8n8.x4.shared.b16 {%0,%1,%2,%3}, [%4];"
                 : "=r"(r0), "=r"(r1), "=r"(r2), "=r"(r3) : "r"(addr));
}
__device__ __forceinline__ void ldm_x4_t(uint32_t addr, uint32_t& r0, uint32_t& r1,
                                         uint32_t& r2, uint32_t& r3) {
    asm volatile("ldmatrix.sync.aligned.m8n8.x4.trans.shared.b16 {%0,%1,%2,%3}, [%4];"
                 : "=r"(r0), "=r"(r1), "=r"(r2), "=r"(r3) : "r"(addr));
}
__device__ __forceinline__ void mma16816h(float* c, uint32_t a0, uint32_t a1,
                                          uint32_t a2, uint32_t a3,
                                          uint32_t b0, uint32_t b1) {
    asm volatile(
        "mma.sync.aligned.m16n8k16.row.col.f32.f16.f16.f32 "
        "{%0,%1,%2,%3}, {%4,%5,%6,%7}, {%8,%9}, {%0,%1,%2,%3};"
        : "+f"(c[0]), "+f"(c[1]), "+f"(c[2]), "+f"(c[3])
        : "r"(a0), "r"(a1), "r"(a2), "r"(a3), "r"(b0), "r"(b1));
}

// ===========================================================================
// Prep: A' = [Ahi | Alo] fp16 along K.  Input [M][1152] fp32.
// ===========================================================================
__global__ void split_A2(const float4* __restrict__ X, __half* __restrict__ ap,
                         int n4)
{
    int i = blockIdx.x * blockDim.x + threadIdx.x;
    if (i >= n4) return;
    int m  = i / (HID / 4);
    int k  = (i % (HID / 4)) * 4;
    float4 x = X[i];
    __half h0 = __float2half(x.x);
    __half h1 = __float2half(x.y);
    __half h2 = __float2half(x.z);
    __half h3 = __float2half(x.w);
    __half l0 = __float2half(x.x - __half2float(h0));
    __half l1 = __float2half(x.y - __half2float(h1));
    __half l2 = __float2half(x.z - __half2float(h2));
    __half l3 = __float2half(x.w - __half2float(h3));
    __half* p = ap + (size_t)m * KP2 + k;
    *(__half2*)(p)           = __half2(h0, h1);
    *(__half2*)(p + 2)       = __half2(h2, h3);
    *(__half2*)(p + HID)     = __half2(l0, l1);
    *(__half2*)(p + HID + 2) = __half2(l2, l3);
}

// Prep: B'T = [Bhi | Bhi] fp16 along K, transposed.
__global__ void split_T2(const float* __restrict__ W, __half* __restrict__ bp,
                         int Nd)
{
    __shared__ float tile[32][33];
    int n0 = blockIdx.x * 32, k0 = blockIdx.y * 32;
    int tx = threadIdx.x, ty = threadIdx.y;   // 32 x 8
    for (int i = ty; i < 32; i += 8)
        tile[i][tx] = W[(size_t)(k0 + i) * Nd + n0 + tx];
    __syncthreads();
    for (int i = ty; i < 32; i += 8) {
        __half h = __float2half(tile[tx][i]);
        __half* row = bp + (size_t)(n0 + i) * KP2;
        row[k0 + tx]       = h;
        row[HID + k0 + tx] = h;
    }
}

// ===========================================================================
// fp16 mma.sync GEMM (R15): 128x128 block, 4 warps (64x64 each), BK=64,
// XOR-swizzled 128B rows, 3-stage ring, 2 blocks/SM.
// ===========================================================================
#define ROWB 128
#define OP_B (128 * ROWB)
#define STAGE_B (2 * OP_B)
#define GEMM_SMEM (3 * STAGE_B)

__global__ __launch_bounds__(128, 2) void mma_gemm(
    const __half* __restrict__ Ap, const __half* __restrict__ Bp,
    const float* __restrict__ bias, float* __restrict__ C, int N)
{
    extern __shared__ __align__(16) char sm[];

    const int t    = threadIdx.x;
    const int wid  = t >> 5;
    const int lane = t & 31;
    const int wm   = wid & 1;
    const int wn   = wid >> 1;
    const int m0   = blockIdx.y * 128;
    const int n0   = blockIdx.x * 128;

    const uint32_t sbase = smem_u32(sm);

    float c[4][8][4];
#pragma unroll
    for (int i = 0; i < 4; i++)
#pragma unroll
        for (int j = 0; j < 8; j++)
#pragma unroll
            for (int q = 0; q < 4; q++) c[i][j][q] = 0.f;

    auto load_stage = [&](int st, int k0) {
        uint32_t sA = sbase + st * STAGE_B;
        uint32_t sB = sA + OP_B;
#pragma unroll
        for (int rep = 0; rep < 8; rep++) {
            int cidx = t + rep * 128;
            int row = cidx >> 3;
            int seg = cidx & 7;
            uint32_t soff = (uint32_t)(row * ROWB + ((seg ^ (row & 7)) << 4));
            cp_async16(sA + soff, Ap + (size_t)(m0 + row) * KP2 + k0 + seg * 8);
            cp_async16(sB + soff, Bp + (size_t)(n0 + row) * KP2 + k0 + seg * 8);
        }
    };

    load_stage(0, 0);   CP_COMMIT();
    load_stage(1, 64);  CP_COMMIT();

    const int arow = lane & 15;
    const int ach  = lane >> 4;
    const int bg   = lane >> 3;
    const int brow = lane & 7;
    const int bnt  = bg >> 1;
    const int bch  = bg & 1;

    int cur = 0;
    for (int kt = 0; kt < NSTG; kt++) {
        CP_WAIT1();
        __syncthreads();

        int pf = cur + 2; if (pf >= 3) pf -= 3;
        if (kt + 2 < NSTG) load_stage(pf, (kt + 2) * 64);
        CP_COMMIT();

        const uint32_t sA = sbase + cur * STAGE_B;
        const uint32_t sB = sA + OP_B;

#pragma unroll
        for (int kk = 0; kk < 4; kk++) {
            uint32_t a[4][4];
#pragma unroll
            for (int mt = 0; mt < 4; mt++) {
                int row = wm * 64 + mt * 16 + arow;
                int lch = 2 * kk + ach;
                uint32_t addr = sA + (uint32_t)(row * ROWB + ((lch ^ (row & 7)) << 4));
                ldm_x4(addr, a[mt][0], a[mt][1], a[mt][2], a[mt][3]);
            }
            uint32_t b[8][2];
#pragma unroll
            for (int p = 0; p < 4; p++) {
                int row = wn * 64 + p * 16 + bnt * 8 + brow;
                int lch = 2 * kk + bch;
                uint32_t addr = sB + (uint32_t)(row * ROWB + ((lch ^ (row & 7)) << 4));
                uint32_t r0, r1, r2, r3;
                ldm_x4(addr, r0, r1, r2, r3);
                b[p * 2][0] = r0; b[p * 2][1] = r1;
                b[p * 2 + 1][0] = r2; b[p * 2 + 1][1] = r3;
            }
#pragma unroll
            for (int mt = 0; mt < 4; mt++)
#pragma unroll
                for (int nt = 0; nt < 8; nt++)
                    mma16816h(c[mt][nt], a[mt][0], a[mt][1], a[mt][2], a[mt][3],
                              b[nt][0], b[nt][1]);
        }
        cur++; if (cur == 3) cur = 0;
    }

    const int qrow = lane >> 2;
    const int qcol = (lane & 3) * 2;
#pragma unroll
    for (int nt = 0; nt < 8; nt++) {
        int col = n0 + wn * 64 + nt * 8 + qcol;
        float b0 = bias[col], b1 = bias[col + 1];
#pragma unroll
        for (int mt = 0; mt < 4; mt++) {
            int r0 = m0 + wm * 64 + mt * 16 + qrow;
            float2 v0 = make_float2(c[mt][nt][0] + b0, c[mt][nt][1] + b1);
            float2 v1 = make_float2(c[mt][nt][2] + b0, c[mt][nt][3] + b1);
            *(float2*)(C + (size_t)r0 * N + col)       = v0;
            *(float2*)(C + (size_t)(r0 + 8) * N + col) = v1;
        }
    }
}

// ===========================================================================
// RoPE + split for attention operands, 2-wide vectorized (d-pairs).
// Q' fp16 [hi|lo] (scaled), K' fp16 [hi|hi], depth 144 pad 160.
// V fp16 with l-column: vh[...][72] = 1.0.
// ===========================================================================
__global__ void rope_split(const float* __restrict__ qkv,
                           const float* __restrict__ cosb,
                           const float* __restrict__ sinb,
                           __half* __restrict__ qp,
                           __half* __restrict__ kp,
                           __half* __restrict__ vh)
{
    int idx = blockIdx.x * blockDim.x + threadIdx.x;   // S*NH*18
    if (idx >= S_TOT * NH * 18) return;
    int pr  = idx % 18;
    int tmp = idx / 18;
    int h   = tmp % NH;
    int s   = tmp / NH;
    int d   = 2 * pr;

    float2 cs = *(const float2*)(cosb + s * HD + d);
    float2 sn = *(const float2*)(sinb + s * HD + d);
    size_t ib = (size_t)s * H3 + h * HD + d;

    float2 qa = *(const float2*)(qkv + ib);
    float2 qb = *(const float2*)(qkv + ib + 36);
    float rq0a = (qa.x * cs.x - qb.x * sn.x) * QSCALE;
    float rq0b = (qa.y * cs.y - qb.y * sn.y) * QSCALE;
    float rq1a = (qb.x * cs.x + qa.x * sn.x) * QSCALE;
    float rq1b = (qb.y * cs.y + qa.y * sn.y) * QSCALE;

    float2 ka = *(const float2*)(qkv + ib + HID);
    float2 kb = *(const float2*)(qkv + ib + HID + 36);
    float rk0a = ka.x * cs.x - kb.x * sn.x;
    float rk0b = ka.y * cs.y - kb.y * sn.y;
    float rk1a = kb.x * cs.x + ka.x * sn.x;
    float rk1b = kb.y * cs.y + ka.y * sn.y;

    float2 va = *(const float2*)(qkv + ib + 2 * HID);
    float2 vb = *(const float2*)(qkv + ib + 2 * HID + 36);

    size_t ob = ((size_t)s * NH + h) * QKP;

    // Q' = [hi | lo]
    {
        __half h0a = __float2half(rq0a), h0b = __float2half(rq0b);
        __half h1a = __float2half(rq1a), h1b = __float2half(rq1b);
        *(__half2*)(qp + ob + d)           = __half2(h0a, h0b);
        *(__half2*)(qp + ob + d + 36)      = __half2(h1a, h1b);
        *(__half2*)(qp + ob + 72 + d)      =
            __half2(__float2half(rq0a - __half2float(h0a)),
                    __float2half(rq0b - __half2float(h0b)));
        *(__half2*)(qp + ob + 72 + d + 36) =
            __half2(__float2half(rq1a - __half2float(h1a)),
                    __float2half(rq1b - __half2float(h1b)));
    }
    // K' = [hi | hi]
    {
        __half2 k0(__float2half(rk0a), __float2half(rk0b));
        __half2 k1(__float2half(rk1a), __float2half(rk1b));
        *(__half2*)(kp + ob + d)           = k0;
        *(__half2*)(kp + ob + d + 36)      = k1;
        *(__half2*)(kp + ob + 72 + d)      = k0;
        *(__half2*)(kp + ob + 72 + d + 36) = k1;
    }

    size_t vbi = ((size_t)s * NH + h) * 80;
    *(__half2*)(vh + vbi + d)      = __floats2half2_rn(va.x, va.y);
    *(__half2*)(vh + vbi + d + 36) = __floats2half2_rn(vb.x, vb.y);

    if (pr < 8) {
        // pads: Q'/K' dims 144..159 = 0
        __half2 z2 = __floats2half2_rn(0.f, 0.f);
        *(__half2*)(qp + ob + 144 + 2 * pr) = z2;
        *(__half2*)(kp + ob + 144 + 2 * pr) = z2;
        if (pr < 4)
            *(__half2*)(vh + vbi + 72 + 2 * pr) =
                (pr == 0) ? __floats2half2_rn(1.f, 0.f) : z2;
    }
}

// ===========================================================================
// FA2-style mma attention (exp2 domain), BQ=128, 3-stage KV ring.
// QK in fp16 split-2 (depth 160, 10 k16 steps). Rows 336B (conflict-free).
// l FREE via V ones-column. Epilogue writes fp16 [hi|lo] ctx into g_ap.
// ===========================================================================
#define QROWB 336                              // 160 fp16 = 320B, pad to 336
#define SQ_BYTES (128 * QROWB)                 // 43,008
#define SK_BYTES (64 * QROWB)                  // 21,504
#define SV_BYTES (64 * 176)                    // 11,264
#define KV_STAGE (SK_BYTES + SV_BYTES)         // 32,768
#define ATT_SMEM (SQ_BYTES + 3 * KV_STAGE)     // 141,312

__global__ __launch_bounds__(256, 1) void attn_mma(
    const __half* __restrict__ Qp, const __half* __restrict__ Kp,
    const __half* __restrict__ Vh, __half* __restrict__ ap)
{
    extern __shared__ char smA[];
    char* sQ  = smA;
    char* sKV = smA + SQ_BYTES;

    const int t    = threadIdx.x;
    const int lane = t & 31;
    const int wid  = t >> 5;
    const int qt   = blockIdx.x;
    const int h    = blockIdx.y;
    const int seg  = blockIdx.z;
    const int sbase = seg * LSEG;
    const int qbase = sbase + qt * 128;
    const int q0    = wid * 16;

    auto load_q = [&]() {
        for (int c = t; c < 128 * 20; c += 256) {
            int row = c / 20, ch = c % 20;
            cp_async16(smem_u32(sQ + row * QROWB + ch * 16),
                       Qp + ((size_t)(qbase + row) * NH + h) * QKP + ch * 8);
        }
    };
    auto load_kv = [&](int st, int kb) {
        char* dk = sKV + st * KV_STAGE;
        char* dv = dk + SK_BYTES;
        for (int c = t; c < 64 * 20 + 64 * 10; c += 256) {
            if (c < 1280) {
                int row = c / 20, ch = c % 20;
                cp_async16(smem_u32(dk + row * QROWB + ch * 16),
                           Kp + ((size_t)(sbase + kb + row) * NH + h) * QKP + ch * 8);
            } else {
                int c2 = c - 1280;
                int row = c2 / 10, ch = c2 % 10;
                cp_async16(smem_u32(dv + row * 176 + ch * 16),
                           Vh + ((size_t)(sbase + kb + row) * NH + h) * 80 + ch * 8);
            }
        }
    };

    load_q(); load_kv(0, 0); CP_COMMIT();
    load_kv(1, 64); CP_COMMIT();

    uint32_t qf[10][4];
    float o[10][4];
#pragma unroll
    for (int j = 0; j < 10; j++)
#pragma unroll
        for (int q = 0; q < 4; q++) o[j][q] = 0.f;
    float m0v = -1e30f, m1v = -1e30f;

    const int qlrow = lane % 16;
    const int qlcol = (lane / 16) * 16;
    const int bkey  = (lane / 16) * 8 + (lane % 8);
    const int bkoff = ((lane / 8) & 1) * 16;
    const int vkey  = ((lane / 8) & 1) * 8 + (lane % 8);
    const int vdoff = (lane / 16) * 16;

    int cur = 0;
    for (int kt = 0; kt < 16; kt++) {
        CP_WAIT1();
        __syncthreads();

        int pf = cur + 2; if (pf >= 3) pf -= 3;
        if (kt + 2 < 16) load_kv(pf, (kt + 2) * 64);
        CP_COMMIT();

        if (kt == 0) {
#pragma unroll
            for (int kk = 0; kk < 10; kk++) {
                uint32_t addr = smem_u32(sQ + (q0 + qlrow) * QROWB + kk * 32 + qlcol);
                ldm_x4(addr, qf[kk][0], qf[kk][1], qf[kk][2], qf[kk][3]);
            }
        }

        const char* bk = sKV + cur * KV_STAGE;
        const char* bv = bk + SK_BYTES;

        float s[8][4];
#pragma unroll
        for (int j = 0; j < 8; j++)
#pragma unroll
            for (int q = 0; q < 4; q++) s[j][q] = 0.f;

#pragma unroll
        for (int kk = 0; kk < 10; kk++) {
#pragma unroll
            for (int pr = 0; pr < 4; pr++) {
                uint32_t addr = smem_u32(bk + (pr * 16 + bkey) * QROWB + kk * 32 + bkoff);
                uint32_t r0, r1, r2, r3;
                ldm_x4(addr, r0, r1, r2, r3);
                mma16816h(s[pr * 2],     qf[kk][0], qf[kk][1], qf[kk][2], qf[kk][3], r0, r1);
                mma16816h(s[pr * 2 + 1], qf[kk][0], qf[kk][1], qf[kk][2], qf[kk][3], r2, r3);
            }
        }

        float rx0 = -1e30f, rx1 = -1e30f;
#pragma unroll
        for (int j = 0; j < 8; j++) {
            rx0 = fmaxf(rx0, fmaxf(s[j][0], s[j][1]));
            rx1 = fmaxf(rx1, fmaxf(s[j][2], s[j][3]));
        }
        rx0 = fmaxf(rx0, __shfl_xor_sync(0xffffffffu, rx0, 1));
        rx0 = fmaxf(rx0, __shfl_xor_sync(0xffffffffu, rx0, 2));
        rx1 = fmaxf(rx1, __shfl_xor_sync(0xffffffffu, rx1, 1));
        rx1 = fmaxf(rx1, __shfl_xor_sync(0xffffffffu, rx1, 2));

        float mn0 = fmaxf(m0v, rx0), mn1 = fmaxf(m1v, rx1);
        float a0 = exp2f(m0v - mn0), a1 = exp2f(m1v - mn1);
        m0v = mn0; m1v = mn1;

#pragma unroll
        for (int j = 0; j < 8; j++) {
            s[j][0] = exp2f(s[j][0] - mn0);
            s[j][1] = exp2f(s[j][1] - mn0);
            s[j][2] = exp2f(s[j][2] - mn1);
            s[j][3] = exp2f(s[j][3] - mn1);
        }

#pragma unroll
        for (int j = 0; j < 10; j++) {
            o[j][0] *= a0; o[j][1] *= a0;
            o[j][2] *= a1; o[j][3] *= a1;
        }

        uint32_t pa[4][4];
#pragma unroll
        for (int kk2 = 0; kk2 < 4; kk2++) {
            int j = 2 * kk2;
            __half2 h0 = __floats2half2_rn(s[j][0],     s[j][1]);
            __half2 h1 = __floats2half2_rn(s[j][2],     s[j][3]);
            __half2 h2 = __floats2half2_rn(s[j + 1][0], s[j + 1][1]);
            __half2 h3 = __floats2half2_rn(s[j + 1][2], s[j + 1][3]);
            pa[kk2][0] = *(uint32_t*)&h0;
            pa[kk2][1] = *(uint32_t*)&h1;
            pa[kk2][2] = *(uint32_t*)&h2;
            pa[kk2][3] = *(uint32_t*)&h3;
        }

#pragma unroll
        for (int kk2 = 0; kk2 < 4; kk2++) {
#pragma unroll
            for (int vp = 0; vp < 5; vp++) {
                uint32_t addr = smem_u32(bv + (kk2 * 16 + vkey) * 176 + vp * 32 + vdoff);
                uint32_t r0, r1, r2, r3;
                ldm_x4_t(addr, r0, r1, r2, r3);
                mma16816h(o[vp * 2],     pa[kk2][0], pa[kk2][1], pa[kk2][2], pa[kk2][3], r0, r1);
                mma16816h(o[vp * 2 + 1], pa[kk2][0], pa[kk2][1], pa[kk2][2], pa[kk2][3], r2, r3);
            }
        }

        cur++; if (cur == 3) cur = 0;
    }

    float l0 = __shfl_sync(0xffffffffu, o[9][0], lane & ~3);
    float l1 = __shfl_sync(0xffffffffu, o[9][2], lane & ~3);
    float inv0 = 1.f / l0, inv1 = 1.f / l1;

    int r_lo = qbase + q0 + lane / 4;
    int r_hi = r_lo + 8;
#pragma unroll
    for (int j = 0; j < 9; j++) {
        int col = h * HD + j * 8 + (lane & 3) * 2;
        float x0 = o[j][0] * inv0, x1 = o[j][1] * inv0;
        float x2 = o[j][2] * inv1, x3 = o[j][3] * inv1;

        __half hx0 = __float2half(x0);
        __half hx1 = __float2half(x1);
        __half lx0 = __float2half(x0 - __half2float(hx0));
        __half lx1 = __float2half(x1 - __half2float(hx1));
        __half* row0 = ap + (size_t)r_lo * KP2 + col;
        *(__half2*)(row0)       = __half2(hx0, hx1);
        *(__half2*)(row0 + HID) = __half2(lx0, lx1);

        __half hx2 = __float2half(x2);
        __half hx3 = __float2half(x3);
        __half lx2 = __float2half(x2 - __half2float(hx2));
        __half lx3 = __float2half(x3 - __half2float(hx3));
        __half* row1 = ap + (size_t)r_hi * KP2 + col;
        *(__half2*)(row1)       = __half2(hx2, hx3);
        *(__half2*)(row1 + HID) = __half2(lx2, lx3);
    }
}

// ===========================================================================
// Launch
// ===========================================================================
extern "C" void kernel_launch(void* const* d_in, const int* in_sizes, int n_in,
                              void* d_out, int out_size)
{
    const float* hidden = (const float*)d_in[0];
    const float* cosb   = (const float*)d_in[1];
    const float* sinb   = (const float*)d_in[2];
    const float* Wqkv   = (const float*)d_in[3];
    const float* bqkv   = (const float*)d_in[4];
    const float* Wout   = (const float*)d_in[5];
    const float* bout   = (const float*)d_in[6];
    float* out = (float*)d_out;

    float *qkv;
    __half *ap, *wqp, *wop, *vh, *qp, *kp2;
    cudaGetSymbolAddress((void**)&qkv, g_qkv);
    cudaGetSymbolAddress((void**)&ap, g_ap);
    cudaGetSymbolAddress((void**)&wqp, g_wqp);
    cudaGetSymbolAddress((void**)&wop, g_wop);
    cudaGetSymbolAddress((void**)&qp, g_qp);
    cudaGetSymbolAddress((void**)&kp2, g_kp2);
    cudaGetSymbolAddress((void**)&vh, g_vh);

    cudaFuncSetAttribute(mma_gemm, cudaFuncAttributeMaxDynamicSharedMemorySize, GEMM_SMEM);
    cudaFuncSetAttribute(attn_mma, cudaFuncAttributeMaxDynamicSharedMemorySize, ATT_SMEM);

    int n4 = S_TOT * HID / 4;

    // Prep: fp16 split-2 operands
    split_A2<<<(n4 + 255) / 256, 256>>>((const float4*)hidden, ap, n4);
    dim3 tb(32, 8);
    split_T2<<<dim3(H3 / 32, HID / 32), tb>>>(Wqkv, wqp, H3);
    split_T2<<<dim3(HID / 32, HID / 32), tb>>>(Wout, wop, HID);

    // 1) QKV projection + bias (tensor cores, fp16 split-2, BK=64)
    mma_gemm<<<dim3(H3 / 128, S_TOT / 128), 128, GEMM_SMEM>>>(ap, wqp, bqkv, qkv, H3);

    // 2) RoPE + attention-operand split (fp16 split-2 Q'/K')
    int nrope = S_TOT * NH * 18;
    rope_split<<<(nrope + 255) / 256, 256>>>(qkv, cosb, sinb, qp, kp2, vh);

    // 3) Attention (tensor cores) -> writes fp16 [hi|lo] ctx into g_ap
    dim3 ga(8, NH, NSEG);
    attn_mma<<<ga, 256, ATT_SMEM>>>(qp, kp2, vh, ap);

    // 4) Output projection + bias (tensor cores, fp16 split-2, BK=64)
    mma_gemm<<<dim3(HID / 128, S_TOT / 128), 128, GEMM_SMEM>>>(ap, wop, bout, out, HID);
}

// round 17
// speedup vs baseline: 1.5185x; 1.0064x over previous
#include <cuda_runtime.h>
#include <cuda_bf16.h>
#include <cuda_fp16.h>
#include <cstdint>
#include <cstddef>

// Problem constants
#define S_TOT  8192
#define HID    1152
#define NH     16
#define HD     72
#define NSEG   8
#define LSEG   1024
#define H3     3456
#define ATT_SCALE 0.11785113019775793f   // 72^-0.5
#define LOG2E     1.4426950408889634f
#define QSCALE    (ATT_SCALE * LOG2E)    // softmax in exp2 domain
#define KP2    2304                      // fp16 split-2 K' = 2*1152 (GEMMs)
#define NSTG   (KP2 / 64)                // 36 k-stages of 64
#define QKP    160                       // attention Q'/K' depth (fp16 split-2): 144 pad 160

// Scratch (allocation-free rule: __device__ globals)
__device__ float g_qkv[(size_t)S_TOT * H3];              // 113 MB
__device__ __half g_ap[(size_t)S_TOT * KP2];             // A' [M][2K] fp16 [hi|lo]
__device__ __half g_wqp[(size_t)H3 * KP2];               // Wqkv'T fp16 [hi|hi]
__device__ __half g_wop[(size_t)HID * KP2];              // Wout'T fp16 [hi|hi]
__device__ __half g_qp[(size_t)S_TOT * NH * QKP];        // Q' fp16 [hi|lo] [s][h][160]
__device__ __half g_kp2[(size_t)S_TOT * NH * QKP];       // K' fp16 [hi|hi]
__device__ __half g_vh[(size_t)S_TOT * NH * 80];         // V fp16; col 72 = 1.0 (l-column)

// ===========================================================================
// PTX helpers (portable sm_80-class only — no tcgen05 on compute_103)
// ===========================================================================
__device__ __forceinline__ uint32_t smem_u32(const void* p) {
    uint32_t a;
    asm("{ .reg .u64 t; cvta.to.shared.u64 t, %1; cvt.u32.u64 %0, t; }"
        : "=r"(a) : "l"(p));
    return a;
}
__device__ __forceinline__ void cp_async16(uint32_t s, const void* g) {
    asm volatile("cp.async.cg.shared.global [%0], [%1], 16;" :: "r"(s), "l"(g));
}
#define CP_COMMIT() asm volatile("cp.async.commit_group;" ::: "memory")
#define CP_WAIT0()  asm volatile("cp.async.wait_group 0;" ::: "memory")
#define CP_WAIT1()  asm volatile("cp.async.wait_group 1;" ::: "memory")

__device__ __forceinline__ void ldm_x4(uint32_t addr, uint32_t& r0, uint32_t& r1,
                                       uint32_t& r2, uint32_t& r3) {
    asm volatile("ldmatrix.sync.aligned.m8n8.x4.shared.b16 {%0,%1,%2,%3}, [%4];"
                 : "=r"(r0), "=r"(r1), "=r"(r2), "=r"(r3) : "r"(addr));
}
__device__ __forceinline__ void ldm_x4_t(uint32_t addr, uint32_t& r0, uint32_t& r1,
                                         uint32_t& r2, uint32_t& r3) {
    asm volatile("ldmatrix.sync.aligned.m8n8.x4.trans.shared.b16 {%0,%1,%2,%3}, [%4];"
                 : "=r"(r0), "=r"(r1), "=r"(r2), "=r"(r3) : "r"(addr));
}
__device__ __forceinline__ void mma16816h(float* c, uint32_t a0, uint32_t a1,
                                          uint32_t a2, uint32_t a3,
                                          uint32_t b0, uint32_t b1) {
    asm volatile(
        "mma.sync.aligned.m16n8k16.row.col.f32.f16.f16.f32 "
        "{%0,%1,%2,%3}, {%4,%5,%6,%7}, {%8,%9}, {%0,%1,%2,%3};"
        : "+f"(c[0]), "+f"(c[1]), "+f"(c[2]), "+f"(c[3])
        : "r"(a0), "r"(a1), "r"(a2), "r"(a3), "r"(b0), "r"(b1));
}
// fp16x2 exp2 (ex2.approx.f16x2)
__device__ __forceinline__ uint32_t h2exp2_u32(float lo, float hi) {
    __half2 d = __floats2half2_rn(lo, hi);
    __half2 e = h2exp2(d);
    return *(uint32_t*)&e;
}

// ===========================================================================
// Prep: A' = [Ahi | Alo] fp16 along K.  Input [M][1152] fp32.
// ===========================================================================
__global__ void split_A2(const float4* __restrict__ X, __half* __restrict__ ap,
                         int n4)
{
    int i = blockIdx.x * blockDim.x + threadIdx.x;
    if (i >= n4) return;
    int m  = i / (HID / 4);
    int k  = (i % (HID / 4)) * 4;
    float4 x = X[i];
    __half h0 = __float2half(x.x);
    __half h1 = __float2half(x.y);
    __half h2 = __float2half(x.z);
    __half h3 = __float2half(x.w);
    __half l0 = __float2half(x.x - __half2float(h0));
    __half l1 = __float2half(x.y - __half2float(h1));
    __half l2 = __float2half(x.z - __half2float(h2));
    __half l3 = __float2half(x.w - __half2float(h3));
    __half* p = ap + (size_t)m * KP2 + k;
    *(__half2*)(p)           = __half2(h0, h1);
    *(__half2*)(p + 2)       = __half2(h2, h3);
    *(__half2*)(p + HID)     = __half2(l0, l1);
    *(__half2*)(p + HID + 2) = __half2(l2, l3);
}

// Prep: B'T = [Bhi | Bhi] fp16 along K, transposed.
__global__ void split_T2(const float* __restrict__ W, __half* __restrict__ bp,
                         int Nd)
{
    __shared__ float tile[32][33];
    int n0 = blockIdx.x * 32, k0 = blockIdx.y * 32;
    int tx = threadIdx.x, ty = threadIdx.y;   // 32 x 8
    for (int i = ty; i < 32; i += 8)
        tile[i][tx] = W[(size_t)(k0 + i) * Nd + n0 + tx];
    __syncthreads();
    for (int i = ty; i < 32; i += 8) {
        __half h = __float2half(tile[tx][i]);
        __half* row = bp + (size_t)(n0 + i) * KP2;
        row[k0 + tx]       = h;
        row[HID + k0 + tx] = h;
    }
}

// ===========================================================================
// fp16 mma.sync GEMM (R15): 128x128 block, 4 warps (64x64 each), BK=64,
// XOR-swizzled 128B rows, 3-stage ring, 2 blocks/SM.
// ===========================================================================
#define ROWB 128
#define OP_B (128 * ROWB)
#define STAGE_B (2 * OP_B)
#define GEMM_SMEM (3 * STAGE_B)

__global__ __launch_bounds__(128, 2) void mma_gemm(
    const __half* __restrict__ Ap, const __half* __restrict__ Bp,
    const float* __restrict__ bias, float* __restrict__ C, int N)
{
    extern __shared__ __align__(16) char sm[];

    const int t    = threadIdx.x;
    const int wid  = t >> 5;
    const int lane = t & 31;
    const int wm   = wid & 1;
    const int wn   = wid >> 1;
    const int m0   = blockIdx.y * 128;
    const int n0   = blockIdx.x * 128;

    const uint32_t sbase = smem_u32(sm);

    float c[4][8][4];
#pragma unroll
    for (int i = 0; i < 4; i++)
#pragma unroll
        for (int j = 0; j < 8; j++)
#pragma unroll
            for (int q = 0; q < 4; q++) c[i][j][q] = 0.f;

    auto load_stage = [&](int st, int k0) {
        uint32_t sA = sbase + st * STAGE_B;
        uint32_t sB = sA + OP_B;
#pragma unroll
        for (int rep = 0; rep < 8; rep++) {
            int cidx = t + rep * 128;
            int row = cidx >> 3;
            int seg = cidx & 7;
            uint32_t soff = (uint32_t)(row * ROWB + ((seg ^ (row & 7)) << 4));
            cp_async16(sA + soff, Ap + (size_t)(m0 + row) * KP2 + k0 + seg * 8);
            cp_async16(sB + soff, Bp + (size_t)(n0 + row) * KP2 + k0 + seg * 8);
        }
    };

    load_stage(0, 0);   CP_COMMIT();
    load_stage(1, 64);  CP_COMMIT();

    const int arow = lane & 15;
    const int ach  = lane >> 4;
    const int bg   = lane >> 3;
    const int brow = lane & 7;
    const int bnt  = bg >> 1;
    const int bch  = bg & 1;

    int cur = 0;
    for (int kt = 0; kt < NSTG; kt++) {
        CP_WAIT1();
        __syncthreads();

        int pf = cur + 2; if (pf >= 3) pf -= 3;
        if (kt + 2 < NSTG) load_stage(pf, (kt + 2) * 64);
        CP_COMMIT();

        const uint32_t sA = sbase + cur * STAGE_B;
        const uint32_t sB = sA + OP_B;

#pragma unroll
        for (int kk = 0; kk < 4; kk++) {
            uint32_t a[4][4];
#pragma unroll
            for (int mt = 0; mt < 4; mt++) {
                int row = wm * 64 + mt * 16 + arow;
                int lch = 2 * kk + ach;
                uint32_t addr = sA + (uint32_t)(row * ROWB + ((lch ^ (row & 7)) << 4));
                ldm_x4(addr, a[mt][0], a[mt][1], a[mt][2], a[mt][3]);
            }
            uint32_t b[8][2];
#pragma unroll
            for (int p = 0; p < 4; p++) {
                int row = wn * 64 + p * 16 + bnt * 8 + brow;
                int lch = 2 * kk + bch;
                uint32_t addr = sB + (uint32_t)(row * ROWB + ((lch ^ (row & 7)) << 4));
                uint32_t r0, r1, r2, r3;
                ldm_x4(addr, r0, r1, r2, r3);
                b[p * 2][0] = r0; b[p * 2][1] = r1;
                b[p * 2 + 1][0] = r2; b[p * 2 + 1][1] = r3;
            }
#pragma unroll
            for (int mt = 0; mt < 4; mt++)
#pragma unroll
                for (int nt = 0; nt < 8; nt++)
                    mma16816h(c[mt][nt], a[mt][0], a[mt][1], a[mt][2], a[mt][3],
                              b[nt][0], b[nt][1]);
        }
        cur++; if (cur == 3) cur = 0;
    }

    const int qrow = lane >> 2;
    const int qcol = (lane & 3) * 2;
#pragma unroll
    for (int nt = 0; nt < 8; nt++) {
        int col = n0 + wn * 64 + nt * 8 + qcol;
        float b0 = bias[col], b1 = bias[col + 1];
#pragma unroll
        for (int mt = 0; mt < 4; mt++) {
            int r0 = m0 + wm * 64 + mt * 16 + qrow;
            float2 v0 = make_float2(c[mt][nt][0] + b0, c[mt][nt][1] + b1);
            float2 v1 = make_float2(c[mt][nt][2] + b0, c[mt][nt][3] + b1);
            *(float2*)(C + (size_t)r0 * N + col)       = v0;
            *(float2*)(C + (size_t)(r0 + 8) * N + col) = v1;
        }
    }
}

// ===========================================================================
// RoPE + split for attention operands, 2-wide vectorized (d-pairs).
// Q' fp16 [hi|lo] (scaled), K' fp16 [hi|hi], depth 144 pad 160.
// V fp16 with l-column: vh[...][72] = 1.0.
// ===========================================================================
__global__ void rope_split(const float* __restrict__ qkv,
                           const float* __restrict__ cosb,
                           const float* __restrict__ sinb,
                           __half* __restrict__ qp,
                           __half* __restrict__ kp,
                           __half* __restrict__ vh)
{
    int idx = blockIdx.x * blockDim.x + threadIdx.x;   // S*NH*18
    if (idx >= S_TOT * NH * 18) return;
    int pr  = idx % 18;
    int tmp = idx / 18;
    int h   = tmp % NH;
    int s   = tmp / NH;
    int d   = 2 * pr;

    float2 cs = *(const float2*)(cosb + s * HD + d);
    float2 sn = *(const float2*)(sinb + s * HD + d);
    size_t ib = (size_t)s * H3 + h * HD + d;

    float2 qa = *(const float2*)(qkv + ib);
    float2 qb = *(const float2*)(qkv + ib + 36);
    float rq0a = (qa.x * cs.x - qb.x * sn.x) * QSCALE;
    float rq0b = (qa.y * cs.y - qb.y * sn.y) * QSCALE;
    float rq1a = (qb.x * cs.x + qa.x * sn.x) * QSCALE;
    float rq1b = (qb.y * cs.y + qa.y * sn.y) * QSCALE;

    float2 ka = *(const float2*)(qkv + ib + HID);
    float2 kb = *(const float2*)(qkv + ib + HID + 36);
    float rk0a = ka.x * cs.x - kb.x * sn.x;
    float rk0b = ka.y * cs.y - kb.y * sn.y;
    float rk1a = kb.x * cs.x + ka.x * sn.x;
    float rk1b = kb.y * cs.y + ka.y * sn.y;

    float2 va = *(const float2*)(qkv + ib + 2 * HID);
    float2 vb = *(const float2*)(qkv + ib + 2 * HID + 36);

    size_t ob = ((size_t)s * NH + h) * QKP;

    // Q' = [hi | lo]
    {
        __half h0a = __float2half(rq0a), h0b = __float2half(rq0b);
        __half h1a = __float2half(rq1a), h1b = __float2half(rq1b);
        *(__half2*)(qp + ob + d)           = __half2(h0a, h0b);
        *(__half2*)(qp + ob + d + 36)      = __half2(h1a, h1b);
        *(__half2*)(qp + ob + 72 + d)      =
            __half2(__float2half(rq0a - __half2float(h0a)),
                    __float2half(rq0b - __half2float(h0b)));
        *(__half2*)(qp + ob + 72 + d + 36) =
            __half2(__float2half(rq1a - __half2float(h1a)),
                    __float2half(rq1b - __half2float(h1b)));
    }
    // K' = [hi | hi]
    {
        __half2 k0(__float2half(rk0a), __float2half(rk0b));
        __half2 k1(__float2half(rk1a), __float2half(rk1b));
        *(__half2*)(kp + ob + d)           = k0;
        *(__half2*)(kp + ob + d + 36)      = k1;
        *(__half2*)(kp + ob + 72 + d)      = k0;
        *(__half2*)(kp + ob + 72 + d + 36) = k1;
    }

    size_t vbi = ((size_t)s * NH + h) * 80;
    *(__half2*)(vh + vbi + d)      = __floats2half2_rn(va.x, va.y);
    *(__half2*)(vh + vbi + d + 36) = __floats2half2_rn(vb.x, vb.y);

    if (pr < 8) {
        __half2 z2 = __floats2half2_rn(0.f, 0.f);
        *(__half2*)(qp + ob + 144 + 2 * pr) = z2;
        *(__half2*)(kp + ob + 144 + 2 * pr) = z2;
        if (pr < 4)
            *(__half2*)(vh + vbi + 72 + 2 * pr) =
                (pr == 0) ? __floats2half2_rn(1.f, 0.f) : z2;
    }
}

// ===========================================================================
// FA2-style mma attention (exp2 domain), BQ=128, 3-stage KV ring.
// QK fp16 split-2 (depth 160); P via ex2.approx.f16x2 (halves MUFU work,
// packing free); l FREE via V ones-column. Writes fp16 [hi|lo] ctx to g_ap.
// ===========================================================================
#define QROWB 336
#define SQ_BYTES (128 * QROWB)
#define SK_BYTES (64 * QROWB)
#define SV_BYTES (64 * 176)
#define KV_STAGE (SK_BYTES + SV_BYTES)
#define ATT_SMEM (SQ_BYTES + 3 * KV_STAGE)     // 141,312

__global__ __launch_bounds__(256, 1) void attn_mma(
    const __half* __restrict__ Qp, const __half* __restrict__ Kp,
    const __half* __restrict__ Vh, __half* __restrict__ ap)
{
    extern __shared__ char smA[];
    char* sQ  = smA;
    char* sKV = smA + SQ_BYTES;

    const int t    = threadIdx.x;
    const int lane = t & 31;
    const int wid  = t >> 5;
    const int qt   = blockIdx.x;
    const int h    = blockIdx.y;
    const int seg  = blockIdx.z;
    const int sbase = seg * LSEG;
    const int qbase = sbase + qt * 128;
    const int q0    = wid * 16;

    auto load_q = [&]() {
        for (int c = t; c < 128 * 20; c += 256) {
            int row = c / 20, ch = c % 20;
            cp_async16(smem_u32(sQ + row * QROWB + ch * 16),
                       Qp + ((size_t)(qbase + row) * NH + h) * QKP + ch * 8);
        }
    };
    auto load_kv = [&](int st, int kb) {
        char* dk = sKV + st * KV_STAGE;
        char* dv = dk + SK_BYTES;
        for (int c = t; c < 64 * 20 + 64 * 10; c += 256) {
            if (c < 1280) {
                int row = c / 20, ch = c % 20;
                cp_async16(smem_u32(dk + row * QROWB + ch * 16),
                           Kp + ((size_t)(sbase + kb + row) * NH + h) * QKP + ch * 8);
            } else {
                int c2 = c - 1280;
                int row = c2 / 10, ch = c2 % 10;
                cp_async16(smem_u32(dv + row * 176 + ch * 16),
                           Vh + ((size_t)(sbase + kb + row) * NH + h) * 80 + ch * 8);
            }
        }
    };

    load_q(); load_kv(0, 0); CP_COMMIT();
    load_kv(1, 64); CP_COMMIT();

    uint32_t qf[10][4];
    float o[10][4];
#pragma unroll
    for (int j = 0; j < 10; j++)
#pragma unroll
        for (int q = 0; q < 4; q++) o[j][q] = 0.f;
    float m0v = -1e30f, m1v = -1e30f;

    const int qlrow = lane % 16;
    const int qlcol = (lane / 16) * 16;
    const int bkey  = (lane / 16) * 8 + (lane % 8);
    const int bkoff = ((lane / 8) & 1) * 16;
    const int vkey  = ((lane / 8) & 1) * 8 + (lane % 8);
    const int vdoff = (lane / 16) * 16;

    int cur = 0;
    for (int kt = 0; kt < 16; kt++) {
        CP_WAIT1();
        __syncthreads();

        int pf = cur + 2; if (pf >= 3) pf -= 3;
        if (kt + 2 < 16) load_kv(pf, (kt + 2) * 64);
        CP_COMMIT();

        if (kt == 0) {
#pragma unroll
            for (int kk = 0; kk < 10; kk++) {
                uint32_t addr = smem_u32(sQ + (q0 + qlrow) * QROWB + kk * 32 + qlcol);
                ldm_x4(addr, qf[kk][0], qf[kk][1], qf[kk][2], qf[kk][3]);
            }
        }

        const char* bk = sKV + cur * KV_STAGE;
        const char* bv = bk + SK_BYTES;

        float s[8][4];
#pragma unroll
        for (int j = 0; j < 8; j++)
#pragma unroll
            for (int q = 0; q < 4; q++) s[j][q] = 0.f;

#pragma unroll
        for (int kk = 0; kk < 10; kk++) {
#pragma unroll
            for (int pr = 0; pr < 4; pr++) {
                uint32_t addr = smem_u32(bk + (pr * 16 + bkey) * QROWB + kk * 32 + bkoff);
                uint32_t r0, r1, r2, r3;
                ldm_x4(addr, r0, r1, r2, r3);
                mma16816h(s[pr * 2],     qf[kk][0], qf[kk][1], qf[kk][2], qf[kk][3], r0, r1);
                mma16816h(s[pr * 2 + 1], qf[kk][0], qf[kk][1], qf[kk][2], qf[kk][3], r2, r3);
            }
        }

        float rx0 = -1e30f, rx1 = -1e30f;
#pragma unroll
        for (int j = 0; j < 8; j++) {
            rx0 = fmaxf(rx0, fmaxf(s[j][0], s[j][1]));
            rx1 = fmaxf(rx1, fmaxf(s[j][2], s[j][3]));
        }
        rx0 = fmaxf(rx0, __shfl_xor_sync(0xffffffffu, rx0, 1));
        rx0 = fmaxf(rx0, __shfl_xor_sync(0xffffffffu, rx0, 2));
        rx1 = fmaxf(rx1, __shfl_xor_sync(0xffffffffu, rx1, 1));
        rx1 = fmaxf(rx1, __shfl_xor_sync(0xffffffffu, rx1, 2));

        float mn0 = fmaxf(m0v, rx0), mn1 = fmaxf(m1v, rx1);
        float a0 = exp2f(m0v - mn0), a1 = exp2f(m1v - mn1);
        m0v = mn0; m1v = mn1;

#pragma unroll
        for (int j = 0; j < 10; j++) {
            o[j][0] *= a0; o[j][1] *= a0;
            o[j][2] *= a1; o[j][3] *= a1;
        }

        // P = exp2(S - m) computed directly in fp16x2 (ex2.approx.f16x2);
        // packing into A-fragments is free.
        uint32_t pa[4][4];
#pragma unroll
        for (int kk2 = 0; kk2 < 4; kk2++) {
            int j = 2 * kk2;
            pa[kk2][0] = h2exp2_u32(s[j][0] - mn0,     s[j][1] - mn0);
            pa[kk2][1] = h2exp2_u32(s[j][2] - mn1,     s[j][3] - mn1);
            pa[kk2][2] = h2exp2_u32(s[j + 1][0] - mn0, s[j + 1][1] - mn0);
            pa[kk2][3] = h2exp2_u32(s[j + 1][2] - mn1, s[j + 1][3] - mn1);
        }

#pragma unroll
        for (int kk2 = 0; kk2 < 4; kk2++) {
#pragma unroll
            for (int vp = 0; vp < 5; vp++) {
                uint32_t addr = smem_u32(bv + (kk2 * 16 + vkey) * 176 + vp * 32 + vdoff);
                uint32_t r0, r1, r2, r3;
                ldm_x4_t(addr, r0, r1, r2, r3);
                mma16816h(o[vp * 2],     pa[kk2][0], pa[kk2][1], pa[kk2][2], pa[kk2][3], r0, r1);
                mma16816h(o[vp * 2 + 1], pa[kk2][0], pa[kk2][1], pa[kk2][2], pa[kk2][3], r2, r3);
            }
        }

        cur++; if (cur == 3) cur = 0;
    }

    float l0 = __shfl_sync(0xffffffffu, o[9][0], lane & ~3);
    float l1 = __shfl_sync(0xffffffffu, o[9][2], lane & ~3);
    float inv0 = 1.f / l0, inv1 = 1.f / l1;

    int r_lo = qbase + q0 + lane / 4;
    int r_hi = r_lo + 8;
#pragma unroll
    for (int j = 0; j < 9; j++) {
        int col = h * HD + j * 8 + (lane & 3) * 2;
        float x0 = o[j][0] * inv0, x1 = o[j][1] * inv0;
        float x2 = o[j][2] * inv1, x3 = o[j][3] * inv1;

        __half hx0 = __float2half(x0);
        __half hx1 = __float2half(x1);
        __half lx0 = __float2half(x0 - __half2float(hx0));
        __half lx1 = __float2half(x1 - __half2float(hx1));
        __half* row0 = ap + (size_t)r_lo * KP2 + col;
        *(__half2*)(row0)       = __half2(hx0, hx1);
        *(__half2*)(row0 + HID) = __half2(lx0, lx1);

        __half hx2 = __float2half(x2);
        __half hx3 = __float2half(x3);
        __half lx2 = __float2half(x2 - __half2float(hx2));
        __half lx3 = __float2half(x3 - __half2float(hx3));
        __half* row1 = ap + (size_t)r_hi * KP2 + col;
        *(__half2*)(row1)       = __half2(hx2, hx3);
        *(__half2*)(row1 + HID) = __half2(lx2, lx3);
    }
}

// ===========================================================================
// Launch
// ===========================================================================
extern "C" void kernel_launch(void* const* d_in, const int* in_sizes, int n_in,
                              void* d_out, int out_size)
{
    const float* hidden = (const float*)d_in[0];
    const float* cosb   = (const float*)d_in[1];
    const float* sinb   = (const float*)d_in[2];
    const float* Wqkv   = (const float*)d_in[3];
    const float* bqkv   = (const float*)d_in[4];
    const float* Wout   = (const float*)d_in[5];
    const float* bout   = (const float*)d_in[6];
    float* out = (float*)d_out;

    float *qkv;
    __half *ap, *wqp, *wop, *vh, *qp, *kp2;
    cudaGetSymbolAddress((void**)&qkv, g_qkv);
    cudaGetSymbolAddress((void**)&ap, g_ap);
    cudaGetSymbolAddress((void**)&wqp, g_wqp);
    cudaGetSymbolAddress((void**)&wop, g_wop);
    cudaGetSymbolAddress((void**)&qp, g_qp);
    cudaGetSymbolAddress((void**)&kp2, g_kp2);
    cudaGetSymbolAddress((void**)&vh, g_vh);

    cudaFuncSetAttribute(mma_gemm, cudaFuncAttributeMaxDynamicSharedMemorySize, GEMM_SMEM);
    cudaFuncSetAttribute(attn_mma, cudaFuncAttributeMaxDynamicSharedMemorySize, ATT_SMEM);

    int n4 = S_TOT * HID / 4;

    // Prep: fp16 split-2 operands
    split_A2<<<(n4 + 255) / 256, 256>>>((const float4*)hidden, ap, n4);
    dim3 tb(32, 8);
    split_T2<<<dim3(H3 / 32, HID / 32), tb>>>(Wqkv, wqp, H3);
    split_T2<<<dim3(HID / 32, HID / 32), tb>>>(Wout, wop, HID);

    // 1) QKV projection + bias (tensor cores, fp16 split-2, BK=64)
    mma_gemm<<<dim3(H3 / 128, S_TOT / 128), 128, GEMM_SMEM>>>(ap, wqp, bqkv, qkv, H3);

    // 2) RoPE + attention-operand split (fp16 split-2 Q'/K')
    int nrope = S_TOT * NH * 18;
    rope_split<<<(nrope + 255) / 256, 256>>>(qkv, cosb, sinb, qp, kp2, vh);

    // 3) Attention (tensor cores) -> writes fp16 [hi|lo] ctx into g_ap
    dim3 ga(8, NH, NSEG);
    attn_mma<<<ga, 256, ATT_SMEM>>>(qp, kp2, vh, ap);

    // 4) Output projection + bias (tensor cores, fp16 split-2, BK=64)
    mma_gemm<<<dim3(HID / 128, S_TOT / 128), 128, GEMM_SMEM>>>(ap, wop, bout, out, HID);
}